// round 1
// baseline (speedup 1.0000x reference)
#include <cuda_runtime.h>
#include <cuda_bf16.h>
#include <cstdint>
#include <cstddef>

// Problem constants
#define BB 8
#define NSEQ 4096
#define NN 32768            // BB*NSEQ nodes
#define H 128
#define EDGES 524288
#define RREL 8
#define NLAYERS 2

// ---------------- scratch (static device globals; no allocation) ----------------
__device__ float g_X[(size_t)NN * H];            // node states (16 MB)
__device__ float g_Z[(size_t)NN * H];            // self-GEMM output / agg accumulator (16 MB)
__device__ float g_Y[(size_t)RREL * NN * H];     // per-relation transformed states (128 MB)
__device__ float g_deg[NN];
__device__ float g_invdeg[NN];

// ---------------- embed: E0 = concept_emb[cid] + kind_emb[kid] -> g_Z ----------------
__global__ __launch_bounds__(256) void embed_kernel(const int* __restrict__ cid,
                                                    const int* __restrict__ kid,
                                                    const float* __restrict__ cemb,
                                                    const float* __restrict__ kemb) {
    int t = blockIdx.x * 256 + threadIdx.x;        // one float4 per thread, NN*32 total
    int node = t >> 5;
    int q = t & 31;
    int c = __ldg(cid + node);
    int k = __ldg(kid + node);
    float4 a = __ldg(((const float4*)(cemb + (size_t)c * H)) + q);
    float4 b = __ldg(((const float4*)(kemb + (size_t)k * H)) + q);
    float4 v;
    v.x = a.x + b.x; v.y = a.y + b.y; v.z = a.z + b.z; v.w = a.w + b.w;
    ((float4*)g_Z)[t] = v;
}

// ---------------- degree ----------------
__global__ __launch_bounds__(256) void zero_deg_kernel() {
    int i = blockIdx.x * 256 + threadIdx.x;
    if (i < NN) g_deg[i] = 0.0f;
}
__global__ __launch_bounds__(256) void deg_kernel(const int* __restrict__ eidx) {
    int e = blockIdx.x * 256 + threadIdx.x;
    if (e < EDGES) atomicAdd(&g_deg[__ldg(eidx + EDGES + e)], 1.0f);
}
__global__ __launch_bounds__(256) void invdeg_kernel() {
    int i = blockIdx.x * 256 + threadIdx.x;
    if (i < NN) g_invdeg[i] = 1.0f / fmaxf(g_deg[i], 1.0f);
}

// ---------------- 128x128x128 fp32 tile GEMM: O = A @ W^T (+bias) ----------------
// A: [M,128] row-major, W: [128(g),128(k)] row-major, O: [M,128].
// Block: 256 threads, tile 128 rows, full K=128 in 8 chunks of 16.
__device__ __forceinline__ void gemm_128x128(const float* __restrict__ A,
                                             const float* __restrict__ W,
                                             const float* __restrict__ bias,
                                             float* __restrict__ O, int m0) {
    __shared__ float As[16][132];   // k-major: As[k][m]
    __shared__ float Bs[16][132];   // k-major: Bs[k][g]
    const int tid = threadIdx.x;
    const int tx = tid & 15;        // column group
    const int ty = tid >> 4;        // row group

    float acc[8][8];
#pragma unroll
    for (int i = 0; i < 8; i++)
#pragma unroll
        for (int j = 0; j < 8; j++) acc[i][j] = 0.0f;

#pragma unroll 1
    for (int k0 = 0; k0 < H; k0 += 16) {
#pragma unroll
        for (int it = 0; it < 2; it++) {
            int idx = tid + it * 256;     // 0..511
            int row = idx >> 2;           // 0..127
            int kq = idx & 3;             // float4 within k-chunk
            float4 v = *(const float4*)(A + (size_t)(m0 + row) * H + k0 + kq * 4);
            As[kq * 4 + 0][row] = v.x;
            As[kq * 4 + 1][row] = v.y;
            As[kq * 4 + 2][row] = v.z;
            As[kq * 4 + 3][row] = v.w;
            float4 w = *(const float4*)(W + (size_t)row * H + k0 + kq * 4);
            Bs[kq * 4 + 0][row] = w.x;
            Bs[kq * 4 + 1][row] = w.y;
            Bs[kq * 4 + 2][row] = w.z;
            Bs[kq * 4 + 3][row] = w.w;
        }
        __syncthreads();
#pragma unroll
        for (int k = 0; k < 16; k++) {
            float4 a0 = *(const float4*)&As[k][ty * 4];
            float4 a1 = *(const float4*)&As[k][64 + ty * 4];
            float4 b0 = *(const float4*)&Bs[k][tx * 4];
            float4 b1 = *(const float4*)&Bs[k][64 + tx * 4];
            float av[8] = {a0.x, a0.y, a0.z, a0.w, a1.x, a1.y, a1.z, a1.w};
            float bv[8] = {b0.x, b0.y, b0.z, b0.w, b1.x, b1.y, b1.z, b1.w};
#pragma unroll
            for (int i = 0; i < 8; i++)
#pragma unroll
                for (int j = 0; j < 8; j++) acc[i][j] = fmaf(av[i], bv[j], acc[i][j]);
        }
        __syncthreads();
    }

    // epilogue: float4 stores, coalesced 256B segments per half-warp
#pragma unroll
    for (int ih = 0; ih < 2; ih++) {
#pragma unroll
        for (int ii = 0; ii < 4; ii++) {
            int row = m0 + ih * 64 + ty * 4 + ii;
#pragma unroll
            for (int jh = 0; jh < 2; jh++) {
                int col = jh * 64 + tx * 4;
                float4 v;
                v.x = acc[ih * 4 + ii][jh * 4 + 0];
                v.y = acc[ih * 4 + ii][jh * 4 + 1];
                v.z = acc[ih * 4 + ii][jh * 4 + 2];
                v.w = acc[ih * 4 + ii][jh * 4 + 3];
                if (bias) {
                    v.x += bias[col + 0];
                    v.y += bias[col + 1];
                    v.z += bias[col + 2];
                    v.w += bias[col + 3];
                }
                *(float4*)(O + (size_t)row * H + col) = v;
            }
        }
    }
}

__global__ __launch_bounds__(256) void gemm_proj_kernel(const float* __restrict__ projW,
                                                        const float* __restrict__ projb) {
    gemm_128x128(g_Z, projW, projb, g_X, blockIdx.x * 128);
}

// grid.y = 9: m<8 -> Y[m] = X @ rel_W[m]^T ; m==8 -> Z = X @ self_W^T + self_b
__global__ __launch_bounds__(256) void gemm_layer_kernel(const float* __restrict__ relW,
                                                         const float* __restrict__ selfW,
                                                         const float* __restrict__ selfb) {
    int m = blockIdx.y;
    const float* W;
    const float* bias;
    float* O;
    if (m < RREL) {
        W = relW + (size_t)m * H * H;
        bias = nullptr;
        O = g_Y + (size_t)m * NN * H;
    } else {
        W = selfW;
        bias = selfb;
        O = g_Z;
    }
    gemm_128x128(g_X, W, bias, O, blockIdx.x * 128);
}

// ---------------- edge aggregation: Z[dst] += invdeg[dst] * Y[type][src] ----------------
// warp per edge; lane handles one float4 (32 lanes * 4 = 128 floats)
__global__ __launch_bounds__(256) void agg_kernel(const int* __restrict__ eidx,
                                                  const int* __restrict__ etype) {
    int e = (blockIdx.x * 256 + threadIdx.x) >> 5;
    int lane = threadIdx.x & 31;
    if (e >= EDGES) return;
    int src = __ldg(eidx + e);
    int dst = __ldg(eidx + EDGES + e);
    int r = __ldg(etype + e);
    float inv = g_invdeg[dst];
    const float4* yrow = (const float4*)(g_Y + ((size_t)r * NN + src) * H);
    float4 v = __ldg(yrow + lane);
    v.x *= inv; v.y *= inv; v.z *= inv; v.w *= inv;
    atomicAdd(((float4*)(g_Z + (size_t)dst * H)) + lane, v);
}

// ---------------- relu passes ----------------
__global__ __launch_bounds__(256) void relu_X_kernel() {
    int t = blockIdx.x * 256 + threadIdx.x;   // float4 index
    float4 z = ((const float4*)g_Z)[t];
    float4 v;
    v.x = fmaxf(z.x, 0.0f); v.y = fmaxf(z.y, 0.0f);
    v.z = fmaxf(z.z, 0.0f); v.w = fmaxf(z.w, 0.0f);
    ((float4*)g_X)[t] = v;
}

__global__ __launch_bounds__(256) void relu_out_kernel(float* __restrict__ out,
                                                       const int* __restrict__ mask) {
    int t = blockIdx.x * 256 + threadIdx.x;   // float4 index
    int node = t >> 5;
    float m = (float)__ldg(mask + node);
    float4 z = ((const float4*)g_Z)[t];
    float4 v;
    v.x = fmaxf(z.x, 0.0f) * m; v.y = fmaxf(z.y, 0.0f) * m;
    v.z = fmaxf(z.z, 0.0f) * m; v.w = fmaxf(z.w, 0.0f) * m;
    ((float4*)out)[t] = v;
}

// ---------------- launch ----------------
extern "C" void kernel_launch(void* const* d_in, const int* in_sizes, int n_in,
                              void* d_out, int out_size) {
    const int* cid     = (const int*)d_in[0];
    const int* kid     = (const int*)d_in[1];
    const int* mask    = (const int*)d_in[2];
    const int* eidx    = (const int*)d_in[3];
    const int* etype   = (const int*)d_in[4];
    const float* cemb  = (const float*)d_in[5];
    const float* kemb  = (const float*)d_in[6];
    const float* projW = (const float*)d_in[7];
    const float* projb = (const float*)d_in[8];
    const float* selfW = (const float*)d_in[9];
    const float* selfb = (const float*)d_in[10];
    const float* relW  = (const float*)d_in[11];
    float* out = (float*)d_out;

    // embedding gather + degree (independent)
    embed_kernel<<<(NN * 32) / 256, 256>>>(cid, kid, cemb, kemb);
    zero_deg_kernel<<<NN / 256, 256>>>();
    deg_kernel<<<EDGES / 256, 256>>>(eidx);
    invdeg_kernel<<<NN / 256, 256>>>();

    // projection: X = E0 @ projW^T + projb
    gemm_proj_kernel<<<NN / 128, 256>>>(projW, projb);

    for (int l = 0; l < NLAYERS; l++) {
        gemm_layer_kernel<<<dim3(NN / 128, RREL + 1), 256>>>(
            relW + (size_t)l * RREL * H * H,
            selfW + (size_t)l * H * H,
            selfb + (size_t)l * H);
        agg_kernel<<<EDGES / 8, 256>>>(eidx, etype);
        if (l == 0)
            relu_X_kernel<<<(NN * 32) / 256, 256>>>();
        else
            relu_out_kernel<<<(NN * 32) / 256, 256>>>(out, mask);
    }
}

// round 4
// speedup vs baseline: 1.4356x; 1.4356x over previous
#include <cuda_runtime.h>
#include <cuda_bf16.h>
#include <cstdint>
#include <cstddef>

// Problem constants
#define BB 8
#define NSEQ 4096
#define NN 32768            // BB*NSEQ nodes
#define H 128
#define EDGES 524288
#define RREL 8
#define NLAYERS 2

#define PITCH 136           // bf16 elems per smem row (272B = 17 x 16B chunks)

// ---------------- scratch (static device globals; no allocation) ----------------
__device__ float g_Z[(size_t)NN * H];            // self-GEMM out / agg accumulator (16 MB)
__device__ float g_Y[(size_t)RREL * NN * H];     // per-relation transformed states (128 MB)
__device__ __nv_bfloat16 g_Xh[(size_t)NN * H];   // hi split of current node states (8 MB)
__device__ __nv_bfloat16 g_Xl[(size_t)NN * H];   // lo split (8 MB)
__device__ __nv_bfloat16 g_Wh[(size_t)(RREL + 1) * H * H];
__device__ __nv_bfloat16 g_Wl[(size_t)(RREL + 1) * H * H];
__device__ float g_deg[NN];
__device__ float g_invdeg[NN];

// ---------------- helpers ----------------
__device__ __forceinline__ uint32_t smem_u32(const void* p) {
    uint32_t a;
    asm("{ .reg .u64 t; cvta.to.shared.u64 t, %1; cvt.u32.u64 %0, t; }" : "=r"(a) : "l"(p));
    return a;
}
__device__ __forceinline__ void ldm_x4(uint32_t& r0, uint32_t& r1, uint32_t& r2, uint32_t& r3,
                                       uint32_t addr) {
    asm volatile("ldmatrix.sync.aligned.m8n8.x4.shared.b16 {%0,%1,%2,%3}, [%4];"
                 : "=r"(r0), "=r"(r1), "=r"(r2), "=r"(r3) : "r"(addr));
}
__device__ __forceinline__ void mma16816(float* d, const uint32_t* a, uint32_t b0, uint32_t b1) {
    asm volatile(
        "mma.sync.aligned.m16n8k16.row.col.f32.bf16.bf16.f32 "
        "{%0,%1,%2,%3}, {%4,%5,%6,%7}, {%8,%9}, {%0,%1,%2,%3};"
        : "+f"(d[0]), "+f"(d[1]), "+f"(d[2]), "+f"(d[3])
        : "r"(a[0]), "r"(a[1]), "r"(a[2]), "r"(a[3]), "r"(b0), "r"(b1));
}
__device__ __forceinline__ void split_bf16(float v, __nv_bfloat16& hi, __nv_bfloat16& lo) {
    hi = __float2bfloat16(v);
    lo = __float2bfloat16(v - __bfloat162float(hi));
}

// ---------------- embed: splits of (concept_emb[cid] + kind_emb[kid]) -> Xh/Xl --------
__global__ __launch_bounds__(256) void embed_kernel(const int* __restrict__ cid,
                                                    const int* __restrict__ kid,
                                                    const float* __restrict__ cemb,
                                                    const float* __restrict__ kemb) {
    int t = blockIdx.x * 256 + threadIdx.x;        // one float4 per thread
    int node = t >> 5;
    int q = t & 31;
    int c = __ldg(cid + node);
    int k = __ldg(kid + node);
    float4 a = __ldg(((const float4*)(cemb + (size_t)c * H)) + q);
    float4 b = __ldg(((const float4*)(kemb + (size_t)k * H)) + q);
    float v[4] = {a.x + b.x, a.y + b.y, a.z + b.z, a.w + b.w};
    __nv_bfloat16 hi[4], lo[4];
#pragma unroll
    for (int i = 0; i < 4; i++) split_bf16(v[i], hi[i], lo[i]);
    ((uint2*)g_Xh)[t] = *(const uint2*)hi;
    ((uint2*)g_Xl)[t] = *(const uint2*)lo;
}

// ---------------- degree ----------------
__global__ __launch_bounds__(256) void zero_deg_kernel() {
    int i = blockIdx.x * 256 + threadIdx.x;
    if (i < NN) g_deg[i] = 0.0f;
}
__global__ __launch_bounds__(256) void deg_kernel(const int* __restrict__ eidx) {
    int e = blockIdx.x * 256 + threadIdx.x;
    if (e < EDGES) atomicAdd(&g_deg[__ldg(eidx + EDGES + e)], 1.0f);
}
__global__ __launch_bounds__(256) void invdeg_kernel() {
    int i = blockIdx.x * 256 + threadIdx.x;
    if (i < NN) g_invdeg[i] = 1.0f / fmaxf(g_deg[i], 1.0f);
}

// ---------------- weight split conversion ----------------
__global__ __launch_bounds__(256) void convert_w_kernel(const float* __restrict__ src,
                                                        int dst_off, int count) {
    int t = blockIdx.x * 256 + threadIdx.x;   // 8 floats per thread
    if (t * 8 >= count) return;
    const float4* s = (const float4*)src;
    float4 a = s[2 * t], b = s[2 * t + 1];
    float v[8] = {a.x, a.y, a.z, a.w, b.x, b.y, b.z, b.w};
    __nv_bfloat16 hi[8], lo[8];
#pragma unroll
    for (int i = 0; i < 8; i++) split_bf16(v[i], hi[i], lo[i]);
    ((uint4*)(g_Wh + dst_off))[t] = *(const uint4*)hi;
    ((uint4*)(g_Wl + dst_off))[t] = *(const uint4*)lo;
}

// ---------------- 128x128x128 split-bf16 HMMA tile GEMM ----------------
// O[m][g] = sum_k A[m][k]*W[g][k] (+bias); A,W given as hi/lo bf16 splits.
// OUT_MODE 0: fp32 -> O.  OUT_MODE 1: split bf16 -> Oh/Ol (in place over A is safe).
template <int OUT_MODE>
__device__ __forceinline__ void tile_gemm(const __nv_bfloat16* __restrict__ Ah_g,
                                          const __nv_bfloat16* __restrict__ Al_g,
                                          const __nv_bfloat16* __restrict__ Wh_g,
                                          const __nv_bfloat16* __restrict__ Wl_g,
                                          const float* __restrict__ bias,
                                          float* __restrict__ O,
                                          __nv_bfloat16* __restrict__ Oh,
                                          __nv_bfloat16* __restrict__ Ol, int m0) {
    extern __shared__ __nv_bfloat16 sm[];
    __nv_bfloat16* sAh = sm;
    __nv_bfloat16* sAl = sAh + 128 * PITCH;
    __nv_bfloat16* sWh = sAl + 128 * PITCH;
    __nv_bfloat16* sWl = sWh + 128 * PITCH;
    const int tid = threadIdx.x;

    // global -> smem (padded rows). Tile = 128 rows x 128 bf16 = 2048 uint4 chunks,
    // 16 chunks (of 8 bf16) per row.
    {
        const __nv_bfloat16* srcs[4] = {Ah_g + (size_t)m0 * H, Al_g + (size_t)m0 * H, Wh_g, Wl_g};
        __nv_bfloat16* dsts[4] = {sAh, sAl, sWh, sWl};
#pragma unroll
        for (int op = 0; op < 4; op++) {
            const uint4* src = (const uint4*)srcs[op];
            __nv_bfloat16* dst = dsts[op];
#pragma unroll
            for (int it = 0; it < 8; it++) {
                int i = tid + it * 256;       // 0..2047
                int r = i >> 4;               // row 0..127
                int c = i & 15;               // 16B chunk within row
                uint4 v = __ldg(src + i);
                *(uint4*)(dst + r * PITCH + c * 8) = v;
            }
        }
    }
    __syncthreads();

    const int wid = tid >> 5;
    const int lane = tid & 31;
    const int wm = wid >> 2;       // 0..1 : 64-row block
    const int wn = wid & 3;        // 0..3 : 32-col block

    float acc[4][4][4];
#pragma unroll
    for (int i = 0; i < 4; i++)
#pragma unroll
        for (int j = 0; j < 4; j++)
#pragma unroll
            for (int k = 0; k < 4; k++) acc[i][j][k] = 0.0f;

    // ldmatrix base addresses (lane-dependent): row = blockRow + lane%16, chunk = lane/16
    const uint32_t lrow = lane & 15;
    const uint32_t lhalf = lane >> 4;          // 0/1 -> +8 bf16
    uint32_t aAh = smem_u32(sAh) + (((wm * 64 + lrow) * PITCH) + lhalf * 8) * 2;
    uint32_t aAl = smem_u32(sAl) + (((wm * 64 + lrow) * PITCH) + lhalf * 8) * 2;
    uint32_t aWh = smem_u32(sWh) + (((wn * 32 + lrow) * PITCH) + lhalf * 8) * 2;
    uint32_t aWl = smem_u32(sWl) + (((wn * 32 + lrow) * PITCH) + lhalf * 8) * 2;

#pragma unroll 2
    for (int ks = 0; ks < 8; ks++) {
        const uint32_t koff = ks * 32;         // 16 bf16 = 32 bytes
        uint32_t bh[2][4], bl[2][4];
#pragma unroll
        for (int bi = 0; bi < 2; bi++) {
            ldm_x4(bh[bi][0], bh[bi][1], bh[bi][2], bh[bi][3],
                   aWh + bi * (16 * PITCH * 2) + koff);
            ldm_x4(bl[bi][0], bl[bi][1], bl[bi][2], bl[bi][3],
                   aWl + bi * (16 * PITCH * 2) + koff);
        }
#pragma unroll
        for (int mi = 0; mi < 4; mi++) {
            uint32_t ah[4], al[4];
            ldm_x4(ah[0], ah[1], ah[2], ah[3], aAh + mi * (16 * PITCH * 2) + koff);
            ldm_x4(al[0], al[1], al[2], al[3], aAl + mi * (16 * PITCH * 2) + koff);
#pragma unroll
            for (int bi = 0; bi < 2; bi++) {
                mma16816(acc[mi][2 * bi + 0], ah, bh[bi][0], bh[bi][2]);
                mma16816(acc[mi][2 * bi + 1], ah, bh[bi][1], bh[bi][3]);
                mma16816(acc[mi][2 * bi + 0], ah, bl[bi][0], bl[bi][2]);
                mma16816(acc[mi][2 * bi + 1], ah, bl[bi][1], bl[bi][3]);
                mma16816(acc[mi][2 * bi + 0], al, bh[bi][0], bh[bi][2]);
                mma16816(acc[mi][2 * bi + 1], al, bh[bi][1], bh[bi][3]);
            }
        }
    }

    // epilogue
    const int gID = lane >> 2;
    const int tig = lane & 3;
#pragma unroll
    for (int mi = 0; mi < 4; mi++) {
#pragma unroll
        for (int nt = 0; nt < 4; nt++) {
            int col = wn * 32 + nt * 8 + tig * 2;
            float b0 = 0.0f, b1 = 0.0f;
            if (bias) { b0 = __ldg(bias + col); b1 = __ldg(bias + col + 1); }
#pragma unroll
            for (int half = 0; half < 2; half++) {
                int row = m0 + wm * 64 + mi * 16 + gID + half * 8;
                float v0 = acc[mi][nt][2 * half + 0] + b0;
                float v1 = acc[mi][nt][2 * half + 1] + b1;
                if (OUT_MODE == 0) {
                    float2 fv = make_float2(v0, v1);
                    *(float2*)(O + (size_t)row * H + col) = fv;
                } else {
                    __nv_bfloat16 h0, l0, h1, l1;
                    split_bf16(v0, h0, l0);
                    split_bf16(v1, h1, l1);
                    __nv_bfloat162 hv; hv.x = h0; hv.y = h1;
                    __nv_bfloat162 lv; lv.x = l0; lv.y = l1;
                    *(__nv_bfloat162*)(Oh + (size_t)row * H + col) = hv;
                    *(__nv_bfloat162*)(Ol + (size_t)row * H + col) = lv;
                }
            }
        }
    }
}

// proj: X(split) = proj of embed splits, in-place over Xh/Xl
__global__ __launch_bounds__(256, 1) void mma_proj_kernel(const float* __restrict__ projb) {
    tile_gemm<1>(g_Xh, g_Xl, g_Wh, g_Wl, projb, nullptr, g_Xh, g_Xl, blockIdx.x * 128);
}

// grid.y = 9: m<8 -> Y[m] = X @ rel_W[m]^T ; m==8 -> Z = X @ self_W^T + self_b
__global__ __launch_bounds__(256, 1) void mma_layer_kernel(const float* __restrict__ selfb) {
    int m = blockIdx.y;
    const __nv_bfloat16* wh = g_Wh + (size_t)m * H * H;
    const __nv_bfloat16* wl = g_Wl + (size_t)m * H * H;
    float* O = (m < RREL) ? (g_Y + (size_t)m * NN * H) : g_Z;
    const float* bias = (m < RREL) ? nullptr : selfb;
    tile_gemm<0>(g_Xh, g_Xl, wh, wl, bias, O, nullptr, nullptr, blockIdx.x * 128);
}

// ---------------- edge aggregation: Z[dst] += invdeg[dst] * Y[type][src] ----------------
__global__ __launch_bounds__(256) void agg_kernel(const int* __restrict__ eidx,
                                                  const int* __restrict__ etype) {
    int e = (blockIdx.x * 256 + threadIdx.x) >> 5;
    int lane = threadIdx.x & 31;
    if (e >= EDGES) return;
    int src = __ldg(eidx + e);
    int dst = __ldg(eidx + EDGES + e);
    int r = __ldg(etype + e);
    float inv = g_invdeg[dst];
    const float4* yrow = (const float4*)(g_Y + ((size_t)r * NN + src) * H);
    float4 v = __ldg(yrow + lane);
    v.x *= inv; v.y *= inv; v.z *= inv; v.w *= inv;
    atomicAdd(((float4*)(g_Z + (size_t)dst * H)) + lane, v);
}

// ---------------- relu passes ----------------
// layer 0: X(split) = relu(Z)
__global__ __launch_bounds__(256) void relu_split_kernel() {
    int t = blockIdx.x * 256 + threadIdx.x;   // float4 index
    float4 z = ((const float4*)g_Z)[t];
    float v[4] = {fmaxf(z.x, 0.0f), fmaxf(z.y, 0.0f), fmaxf(z.z, 0.0f), fmaxf(z.w, 0.0f)};
    __nv_bfloat16 hi[4], lo[4];
#pragma unroll
    for (int i = 0; i < 4; i++) split_bf16(v[i], hi[i], lo[i]);
    ((uint2*)g_Xh)[t] = *(const uint2*)hi;
    ((uint2*)g_Xl)[t] = *(const uint2*)lo;
}

// layer 1: out = relu(Z) * mask
__global__ __launch_bounds__(256) void relu_out_kernel(float* __restrict__ out,
                                                       const int* __restrict__ mask) {
    int t = blockIdx.x * 256 + threadIdx.x;
    int node = t >> 5;
    float m = (float)__ldg(mask + node);
    float4 z = ((const float4*)g_Z)[t];
    float4 v;
    v.x = fmaxf(z.x, 0.0f) * m; v.y = fmaxf(z.y, 0.0f) * m;
    v.z = fmaxf(z.z, 0.0f) * m; v.w = fmaxf(z.w, 0.0f) * m;
    ((float4*)out)[t] = v;
}

// ---------------- launch ----------------
extern "C" void kernel_launch(void* const* d_in, const int* in_sizes, int n_in,
                              void* d_out, int out_size) {
    const int* cid     = (const int*)d_in[0];
    const int* kid     = (const int*)d_in[1];
    const int* mask    = (const int*)d_in[2];
    const int* eidx    = (const int*)d_in[3];
    const int* etype   = (const int*)d_in[4];
    const float* cemb  = (const float*)d_in[5];
    const float* kemb  = (const float*)d_in[6];
    const float* projW = (const float*)d_in[7];
    const float* projb = (const float*)d_in[8];
    const float* selfW = (const float*)d_in[9];
    const float* selfb = (const float*)d_in[10];
    const float* relW  = (const float*)d_in[11];
    float* out = (float*)d_out;

    const int smem_bytes = 4 * 128 * PITCH * 2;   // 139264
    cudaFuncSetAttribute(mma_proj_kernel, cudaFuncAttributeMaxDynamicSharedMemorySize, smem_bytes);
    cudaFuncSetAttribute(mma_layer_kernel, cudaFuncAttributeMaxDynamicSharedMemorySize, smem_bytes);

    // embedding gather (split output) + degree
    embed_kernel<<<(NN * 32) / 256, 256>>>(cid, kid, cemb, kemb);
    zero_deg_kernel<<<NN / 256, 256>>>();
    deg_kernel<<<EDGES / 256, 256>>>(eidx);
    invdeg_kernel<<<NN / 256, 256>>>();

    // projection: X = E0 @ projW^T + projb (split in/out, in place)
    convert_w_kernel<<<(H * H / 8 + 255) / 256, 256>>>(projW, 0, H * H);
    mma_proj_kernel<<<NN / 128, 256, smem_bytes>>>(projb);

    for (int l = 0; l < NLAYERS; l++) {
        convert_w_kernel<<<(RREL * H * H / 8 + 255) / 256, 256>>>(
            relW + (size_t)l * RREL * H * H, 0, RREL * H * H);
        convert_w_kernel<<<(H * H / 8 + 255) / 256, 256>>>(
            selfW + (size_t)l * H * H, RREL * H * H, H * H);
        mma_layer_kernel<<<dim3(NN / 128, RREL + 1), 256, smem_bytes>>>(selfb);
        agg_kernel<<<EDGES / 8, 256>>>(eidx, etype);
        if (l == 0)
            relu_split_kernel<<<(NN * 32) / 256, 256>>>();
        else
            relu_out_kernel<<<(NN * 32) / 256, 256>>>(out, mask);
    }
}

// round 6
// speedup vs baseline: 1.5533x; 1.0820x over previous
#include <cuda_runtime.h>
#include <cuda_bf16.h>
#include <cstdint>
#include <cstddef>

// Problem constants
#define BB 8
#define NSEQ 4096
#define NN 32768            // BB*NSEQ nodes
#define H 128
#define EDGES 524288
#define RREL 8
#define NLAYERS 2

#define PITCH_W 136         // bf16 elems per W smem row (272B)
#define PITCH_A 40          // bf16 elems per A-chunk smem row (80B; 32 data + 8 pad)

// smem map (bf16 element offsets)
#define SW_H   0
#define SW_L   (128 * PITCH_W)                 // 17408
#define SA_OFF (2 * 128 * PITCH_W)             // 34816
#define SA_SZ  (128 * PITCH_A)                 // 5120 per (buf,h/l)
#define SM_ELEMS (SA_OFF + 4 * SA_SZ)          // 55296 bf16 = 110592 B

// ---------------- scratch (static device globals; no allocation) ----------------
__device__ float g_Z[(size_t)NN * H];            // self-GEMM out / agg accumulator (16 MB)
__device__ float g_Y[(size_t)RREL * NN * H];     // per-relation transformed states (128 MB)
__device__ __nv_bfloat16 g_Xh[(size_t)NN * H];   // hi split of current node states (8 MB)
__device__ __nv_bfloat16 g_Xl[(size_t)NN * H];   // lo split (8 MB)
__device__ __nv_bfloat16 g_Wh[(size_t)(RREL + 1) * H * H];
__device__ __nv_bfloat16 g_Wl[(size_t)(RREL + 1) * H * H];
__device__ float g_deg[NN];
__device__ float g_invdeg[NN];

// ---------------- helpers ----------------
__device__ __forceinline__ uint32_t smem_u32(const void* p) {
    uint32_t a;
    asm("{ .reg .u64 t; cvta.to.shared.u64 t, %1; cvt.u32.u64 %0, t; }" : "=r"(a) : "l"(p));
    return a;
}
__device__ __forceinline__ void cp_async16(uint32_t dst, const void* src) {
    asm volatile("cp.async.cg.shared.global [%0], [%1], 16;" :: "r"(dst), "l"(src));
}
__device__ __forceinline__ void cp_commit() {
    asm volatile("cp.async.commit_group;");
}
__device__ __forceinline__ void cp_wait0() {
    asm volatile("cp.async.wait_group 0;");
}
__device__ __forceinline__ void ldm_x4(uint32_t& r0, uint32_t& r1, uint32_t& r2, uint32_t& r3,
                                       uint32_t addr) {
    asm volatile("ldmatrix.sync.aligned.m8n8.x4.shared.b16 {%0,%1,%2,%3}, [%4];"
                 : "=r"(r0), "=r"(r1), "=r"(r2), "=r"(r3) : "r"(addr));
}
__device__ __forceinline__ void mma16816(float* d, const uint32_t* a, uint32_t b0, uint32_t b1) {
    asm volatile(
        "mma.sync.aligned.m16n8k16.row.col.f32.bf16.bf16.f32 "
        "{%0,%1,%2,%3}, {%4,%5,%6,%7}, {%8,%9}, {%0,%1,%2,%3};"
        : "+f"(d[0]), "+f"(d[1]), "+f"(d[2]), "+f"(d[3])
        : "r"(a[0]), "r"(a[1]), "r"(a[2]), "r"(a[3]), "r"(b0), "r"(b1));
}
__device__ __forceinline__ void split_bf16(float v, __nv_bfloat16& hi, __nv_bfloat16& lo) {
    hi = __float2bfloat16(v);
    lo = __float2bfloat16(v - __bfloat162float(hi));
}

// ---------------- embed: splits of (concept_emb[cid] + kind_emb[kid]) -> Xh/Xl --------
__global__ __launch_bounds__(256) void embed_kernel(const int* __restrict__ cid,
                                                    const int* __restrict__ kid,
                                                    const float* __restrict__ cemb,
                                                    const float* __restrict__ kemb) {
    int t = blockIdx.x * 256 + threadIdx.x;        // one float4 per thread
    int node = t >> 5;
    int q = t & 31;
    int c = __ldg(cid + node);
    int k = __ldg(kid + node);
    float4 a = __ldg(((const float4*)(cemb + (size_t)c * H)) + q);
    float4 b = __ldg(((const float4*)(kemb + (size_t)k * H)) + q);
    float v[4] = {a.x + b.x, a.y + b.y, a.z + b.z, a.w + b.w};
    __nv_bfloat16 hi[4], lo[4];
#pragma unroll
    for (int i = 0; i < 4; i++) split_bf16(v[i], hi[i], lo[i]);
    ((uint2*)g_Xh)[t] = *(const uint2*)hi;
    ((uint2*)g_Xl)[t] = *(const uint2*)lo;
}

// ---------------- degree ----------------
__global__ __launch_bounds__(256) void zero_deg_kernel() {
    int i = blockIdx.x * 256 + threadIdx.x;
    if (i < NN) g_deg[i] = 0.0f;
}
__global__ __launch_bounds__(256) void deg_kernel(const int* __restrict__ eidx) {
    int e = blockIdx.x * 256 + threadIdx.x;
    if (e < EDGES) atomicAdd(&g_deg[__ldg(eidx + EDGES + e)], 1.0f);
}
__global__ __launch_bounds__(256) void invdeg_kernel() {
    int i = blockIdx.x * 256 + threadIdx.x;
    if (i < NN) g_invdeg[i] = 1.0f / fmaxf(g_deg[i], 1.0f);
}

// ---------------- weight split conversion ----------------
__global__ __launch_bounds__(256) void convert_w_kernel(const float* __restrict__ src,
                                                        int dst_off, int count) {
    int t = blockIdx.x * 256 + threadIdx.x;   // 8 floats per thread
    if (t * 8 >= count) return;
    const float4* s = (const float4*)src;
    float4 a = s[2 * t], b = s[2 * t + 1];
    float v[8] = {a.x, a.y, a.z, a.w, b.x, b.y, b.z, b.w};
    __nv_bfloat16 hi[8], lo[8];
#pragma unroll
    for (int i = 0; i < 8; i++) split_bf16(v[i], hi[i], lo[i]);
    ((uint4*)(g_Wh + dst_off))[t] = *(const uint4*)hi;
    ((uint4*)(g_Wl + dst_off))[t] = *(const uint4*)lo;
}

// ---------------- 128x128x128 split-bf16 HMMA tile GEMM (pipelined) ----------------
// O[m][g] = sum_k A[m][k]*W[g][k] (+bias); A,W given as hi/lo bf16 splits.
// W resident in smem; A streamed in 4 k-chunks of 32 with cp.async double buffer.
// One A chunk (per h/l) = 128 rows x 32 bf16 = 8192B = 512 uint4 chunks (4 per row).
// OUT_MODE 0: fp32 -> O.  OUT_MODE 1: split bf16 -> Oh/Ol (in place over A is safe).
template <int OUT_MODE>
__device__ __forceinline__ void tile_gemm(const __nv_bfloat16* __restrict__ Ah_g,
                                          const __nv_bfloat16* __restrict__ Al_g,
                                          const __nv_bfloat16* __restrict__ Wh_g,
                                          const __nv_bfloat16* __restrict__ Wl_g,
                                          const float* __restrict__ bias,
                                          float* __restrict__ O,
                                          __nv_bfloat16* __restrict__ Oh,
                                          __nv_bfloat16* __restrict__ Ol, int m0) {
    extern __shared__ __nv_bfloat16 sm[];
    const uint32_t sbase = smem_u32(sm);
    const int tid = threadIdx.x;

    const __nv_bfloat16* Ag[2] = {Ah_g + (size_t)m0 * H, Al_g + (size_t)m0 * H};

    // ---- prologue: async-load W (hi+lo) and A chunk 0 ----
    {
        const __nv_bfloat16* wsrc[2] = {Wh_g, Wl_g};
#pragma unroll
        for (int hl = 0; hl < 2; hl++) {
#pragma unroll
            for (int it = 0; it < 8; it++) {
                int i = tid + it * 256;       // 0..2047 uint4 chunks (16 per row)
                int r = i >> 4;
                int c = i & 15;
                uint32_t dst = sbase + ((hl ? SW_L : SW_H) + r * PITCH_W + c * 8) * 2;
                cp_async16(dst, wsrc[hl] + r * H + c * 8);
            }
        }
        // A chunk 0 into buf 0: 512 uint4 chunks per h/l (4 per row)
#pragma unroll
        for (int hl = 0; hl < 2; hl++) {
#pragma unroll
            for (int it = 0; it < 2; it++) {
                int i = tid + it * 256;       // 0..511
                int r = i >> 2;               // row 0..127
                int c = i & 3;                // 16B chunk within 64B row
                uint32_t dst = sbase + (SA_OFF + hl * SA_SZ + r * PITCH_A + c * 8) * 2;
                cp_async16(dst, Ag[hl] + r * H + c * 8);
            }
        }
        cp_commit();
        cp_wait0();
    }
    __syncthreads();

    const int wid = tid >> 5;
    const int lane = tid & 31;
    const int wm = wid >> 2;       // 0..1 : 64-row block
    const int wn = wid & 3;        // 0..3 : 32-col block

    float acc[4][4][4];
#pragma unroll
    for (int i = 0; i < 4; i++)
#pragma unroll
        for (int j = 0; j < 4; j++)
#pragma unroll
            for (int k = 0; k < 4; k++) acc[i][j][k] = 0.0f;

    // ldmatrix lane addressing (same recipe as verified R4 kernel)
    const uint32_t lrow = lane & 15;
    const uint32_t lhalf = lane >> 4;          // 0/1 -> +8 bf16
    const uint32_t aWh = sbase + (SW_H + (wn * 32 + lrow) * PITCH_W + lhalf * 8) * 2;
    const uint32_t aWl = sbase + (SW_L + (wn * 32 + lrow) * PITCH_W + lhalf * 8) * 2;
    const uint32_t aA0 = sbase + (SA_OFF + (wm * 64 + lrow) * PITCH_A + lhalf * 8) * 2;

#pragma unroll
    for (int kc = 0; kc < 4; kc++) {
        // issue next A chunk into the other buffer (overlapped with compute)
        if (kc < 3) {
            int b = (kc + 1) & 1;
#pragma unroll
            for (int hl = 0; hl < 2; hl++) {
#pragma unroll
                for (int it = 0; it < 2; it++) {
                    int i = tid + it * 256;   // 0..511
                    int r = i >> 2;
                    int c = i & 3;
                    uint32_t dst = sbase +
                        (SA_OFF + (2 * b + hl) * SA_SZ + r * PITCH_A + c * 8) * 2;
                    cp_async16(dst, Ag[hl] + r * H + (kc + 1) * 32 + c * 8);
                }
            }
            cp_commit();
        }

        const uint32_t aAh = aA0 + (2 * (kc & 1) + 0) * (SA_SZ * 2);
        const uint32_t aAl = aA0 + (2 * (kc & 1) + 1) * (SA_SZ * 2);
#pragma unroll
        for (int kstep = 0; kstep < 2; kstep++) {
            const int ks = kc * 2 + kstep;         // global k-step for W
            const uint32_t wkoff = ks * 32;        // 16 bf16 = 32 bytes
            const uint32_t akoff = kstep * 32;
            uint32_t bh[2][4], bl[2][4];
#pragma unroll
            for (int bi = 0; bi < 2; bi++) {
                ldm_x4(bh[bi][0], bh[bi][1], bh[bi][2], bh[bi][3],
                       aWh + bi * (16 * PITCH_W * 2) + wkoff);
                ldm_x4(bl[bi][0], bl[bi][1], bl[bi][2], bl[bi][3],
                       aWl + bi * (16 * PITCH_W * 2) + wkoff);
            }
#pragma unroll
            for (int mi = 0; mi < 4; mi++) {
                uint32_t ah[4], al[4];
                ldm_x4(ah[0], ah[1], ah[2], ah[3], aAh + mi * (16 * PITCH_A * 2) + akoff);
                ldm_x4(al[0], al[1], al[2], al[3], aAl + mi * (16 * PITCH_A * 2) + akoff);
#pragma unroll
                for (int bi = 0; bi < 2; bi++) {
                    mma16816(acc[mi][2 * bi + 0], ah, bh[bi][0], bh[bi][2]);
                    mma16816(acc[mi][2 * bi + 1], ah, bh[bi][1], bh[bi][3]);
                    mma16816(acc[mi][2 * bi + 0], ah, bl[bi][0], bl[bi][2]);
                    mma16816(acc[mi][2 * bi + 1], ah, bl[bi][1], bl[bi][3]);
                    mma16816(acc[mi][2 * bi + 0], al, bh[bi][0], bh[bi][2]);
                    mma16816(acc[mi][2 * bi + 1], al, bh[bi][1], bh[bi][3]);
                }
            }
        }

        if (kc < 3) {
            cp_wait0();
            __syncthreads();
        }
    }

    // epilogue
    const int gID = lane >> 2;
    const int tig = lane & 3;
#pragma unroll
    for (int mi = 0; mi < 4; mi++) {
#pragma unroll
        for (int nt = 0; nt < 4; nt++) {
            int col = wn * 32 + nt * 8 + tig * 2;
            float b0 = 0.0f, b1 = 0.0f;
            if (bias) { b0 = __ldg(bias + col); b1 = __ldg(bias + col + 1); }
#pragma unroll
            for (int half = 0; half < 2; half++) {
                int row = m0 + wm * 64 + mi * 16 + gID + half * 8;
                float v0 = acc[mi][nt][2 * half + 0] + b0;
                float v1 = acc[mi][nt][2 * half + 1] + b1;
                if (OUT_MODE == 0) {
                    float2 fv = make_float2(v0, v1);
                    *(float2*)(O + (size_t)row * H + col) = fv;
                } else {
                    __nv_bfloat16 h0, l0, h1, l1;
                    split_bf16(v0, h0, l0);
                    split_bf16(v1, h1, l1);
                    __nv_bfloat162 hv; hv.x = h0; hv.y = h1;
                    __nv_bfloat162 lv; lv.x = l0; lv.y = l1;
                    *(__nv_bfloat162*)(Oh + (size_t)row * H + col) = hv;
                    *(__nv_bfloat162*)(Ol + (size_t)row * H + col) = lv;
                }
            }
        }
    }
}

// proj: X(split) = proj of embed splits, in-place over Xh/Xl
__global__ __launch_bounds__(256, 2) void mma_proj_kernel(const float* __restrict__ projb) {
    tile_gemm<1>(g_Xh, g_Xl, g_Wh, g_Wl, projb, nullptr, g_Xh, g_Xl, blockIdx.x * 128);
}

// grid.y = 9: m<8 -> Y[m] = X @ rel_W[m]^T ; m==8 -> Z = X @ self_W^T + self_b
__global__ __launch_bounds__(256, 2) void mma_layer_kernel(const float* __restrict__ selfb) {
    int m = blockIdx.y;
    const __nv_bfloat16* wh = g_Wh + (size_t)m * H * H;
    const __nv_bfloat16* wl = g_Wl + (size_t)m * H * H;
    float* O = (m < RREL) ? (g_Y + (size_t)m * NN * H) : g_Z;
    const float* bias = (m < RREL) ? nullptr : selfb;
    tile_gemm<0>(g_Xh, g_Xl, wh, wl, bias, O, nullptr, nullptr, blockIdx.x * 128);
}

// ---------------- edge aggregation: Z[dst] += invdeg[dst] * Y[type][src] ----------------
__global__ __launch_bounds__(256) void agg_kernel(const int* __restrict__ eidx,
                                                  const int* __restrict__ etype) {
    int e = (blockIdx.x * 256 + threadIdx.x) >> 5;
    int lane = threadIdx.x & 31;
    if (e >= EDGES) return;
    int src = __ldg(eidx + e);
    int dst = __ldg(eidx + EDGES + e);
    int r = __ldg(etype + e);
    float inv = g_invdeg[dst];
    const float4* yrow = (const float4*)(g_Y + ((size_t)r * NN + src) * H);
    float4 v = __ldg(yrow + lane);
    v.x *= inv; v.y *= inv; v.z *= inv; v.w *= inv;
    atomicAdd(((float4*)(g_Z + (size_t)dst * H)) + lane, v);
}

// ---------------- relu passes ----------------
// layer 0: X(split) = relu(Z)
__global__ __launch_bounds__(256) void relu_split_kernel() {
    int t = blockIdx.x * 256 + threadIdx.x;   // float4 index
    float4 z = ((const float4*)g_Z)[t];
    float v[4] = {fmaxf(z.x, 0.0f), fmaxf(z.y, 0.0f), fmaxf(z.z, 0.0f), fmaxf(z.w, 0.0f)};
    __nv_bfloat16 hi[4], lo[4];
#pragma unroll
    for (int i = 0; i < 4; i++) split_bf16(v[i], hi[i], lo[i]);
    ((uint2*)g_Xh)[t] = *(const uint2*)hi;
    ((uint2*)g_Xl)[t] = *(const uint2*)lo;
}

// layer 1: out = relu(Z) * mask
__global__ __launch_bounds__(256) void relu_out_kernel(float* __restrict__ out,
                                                       const int* __restrict__ mask) {
    int t = blockIdx.x * 256 + threadIdx.x;
    int node = t >> 5;
    float m = (float)__ldg(mask + node);
    float4 z = ((const float4*)g_Z)[t];
    float4 v;
    v.x = fmaxf(z.x, 0.0f) * m; v.y = fmaxf(z.y, 0.0f) * m;
    v.z = fmaxf(z.z, 0.0f) * m; v.w = fmaxf(z.w, 0.0f) * m;
    ((float4*)out)[t] = v;
}

// ---------------- launch ----------------
extern "C" void kernel_launch(void* const* d_in, const int* in_sizes, int n_in,
                              void* d_out, int out_size) {
    const int* cid     = (const int*)d_in[0];
    const int* kid     = (const int*)d_in[1];
    const int* mask    = (const int*)d_in[2];
    const int* eidx    = (const int*)d_in[3];
    const int* etype   = (const int*)d_in[4];
    const float* cemb  = (const float*)d_in[5];
    const float* kemb  = (const float*)d_in[6];
    const float* projW = (const float*)d_in[7];
    const float* projb = (const float*)d_in[8];
    const float* selfW = (const float*)d_in[9];
    const float* selfb = (const float*)d_in[10];
    const float* relW  = (const float*)d_in[11];
    float* out = (float*)d_out;

    const int smem_bytes = SM_ELEMS * 2;   // 110592
    cudaFuncSetAttribute(mma_proj_kernel, cudaFuncAttributeMaxDynamicSharedMemorySize, smem_bytes);
    cudaFuncSetAttribute(mma_layer_kernel, cudaFuncAttributeMaxDynamicSharedMemorySize, smem_bytes);

    // embedding gather (split output) + degree
    embed_kernel<<<(NN * 32) / 256, 256>>>(cid, kid, cemb, kemb);
    zero_deg_kernel<<<NN / 256, 256>>>();
    deg_kernel<<<EDGES / 256, 256>>>(eidx);
    invdeg_kernel<<<NN / 256, 256>>>();

    // projection: X = E0 @ projW^T + projb (split in/out, in place)
    convert_w_kernel<<<(H * H / 8 + 255) / 256, 256>>>(projW, 0, H * H);
    mma_proj_kernel<<<NN / 128, 256, smem_bytes>>>(projb);

    for (int l = 0; l < NLAYERS; l++) {
        convert_w_kernel<<<(RREL * H * H / 8 + 255) / 256, 256>>>(
            relW + (size_t)l * RREL * H * H, 0, RREL * H * H);
        convert_w_kernel<<<(H * H / 8 + 255) / 256, 256>>>(
            selfW + (size_t)l * H * H, RREL * H * H, H * H);
        mma_layer_kernel<<<dim3(NN / 128, RREL + 1), 256, smem_bytes>>>(selfb);
        agg_kernel<<<EDGES / 8, 256>>>(eidx, etype);
        if (l == 0)
            relu_split_kernel<<<(NN * 32) / 256, 256>>>();
        else
            relu_out_kernel<<<(NN * 32) / 256, 256>>>(out, mask);
    }
}

// round 7
// speedup vs baseline: 1.8290x; 1.1775x over previous
#include <cuda_runtime.h>
#include <cuda_fp16.h>
#include <cuda_bf16.h>
#include <cstdint>
#include <cstddef>

// Problem constants
#define BB 8
#define NSEQ 4096
#define NN 32768            // BB*NSEQ nodes
#define H 128
#define EDGES 524288
#define RREL 8
#define NLAYERS 2

#define PITCH_W 136         // fp16 elems per W smem row (272B)
#define PITCH_A 40          // fp16 elems per A-chunk smem row (80B; 32 data + 8 pad)

// smem map (fp16 element offsets)
#define SW_H   0
#define SW_L   (128 * PITCH_W)                 // 17408
#define SA_OFF (2 * 128 * PITCH_W)             // 34816
#define SA_SZ  (128 * PITCH_A)                 // 5120 per buffer
#define SM_ELEMS (SA_OFF + 2 * SA_SZ)          // 45056 fp16 = 90112 B

#define NMAT (1 + NLAYERS * (RREL + 1))        // 19 weight matrices
#define SCALE 64.0f
#define INV_SCALE2 (1.0f / 4096.0f)

// ---------------- scratch (static device globals; no allocation) ----------------
__device__ float g_Z[(size_t)NN * H];            // self-GEMM out / agg accumulator (16 MB)
__device__ float g_Y[(size_t)RREL * NN * H];     // per-relation transformed states (128 MB)
__device__ __half g_Xf[(size_t)NN * H];          // node states, fp16 scaled x64 (8 MB)
__device__ __half g_Wh[(size_t)NMAT * H * H];    // weight hi splits (x64)
__device__ __half g_Wl[(size_t)NMAT * H * H];    // weight lo splits
__device__ float g_deg[NN];

// ---------------- helpers ----------------
__device__ __forceinline__ uint32_t smem_u32(const void* p) {
    uint32_t a;
    asm("{ .reg .u64 t; cvta.to.shared.u64 t, %1; cvt.u32.u64 %0, t; }" : "=r"(a) : "l"(p));
    return a;
}
__device__ __forceinline__ void cp_async16(uint32_t dst, const void* src) {
    asm volatile("cp.async.cg.shared.global [%0], [%1], 16;" :: "r"(dst), "l"(src));
}
__device__ __forceinline__ void cp_commit() {
    asm volatile("cp.async.commit_group;");
}
__device__ __forceinline__ void cp_wait0() {
    asm volatile("cp.async.wait_group 0;");
}
__device__ __forceinline__ void ldm_x4(uint32_t& r0, uint32_t& r1, uint32_t& r2, uint32_t& r3,
                                       uint32_t addr) {
    asm volatile("ldmatrix.sync.aligned.m8n8.x4.shared.b16 {%0,%1,%2,%3}, [%4];"
                 : "=r"(r0), "=r"(r1), "=r"(r2), "=r"(r3) : "r"(addr));
}
__device__ __forceinline__ void mma16816(float* d, const uint32_t* a, uint32_t b0, uint32_t b1) {
    asm volatile(
        "mma.sync.aligned.m16n8k16.row.col.f32.f16.f16.f32 "
        "{%0,%1,%2,%3}, {%4,%5,%6,%7}, {%8,%9}, {%0,%1,%2,%3};"
        : "+f"(d[0]), "+f"(d[1]), "+f"(d[2]), "+f"(d[3])
        : "r"(a[0]), "r"(a[1]), "r"(a[2]), "r"(a[3]), "r"(b0), "r"(b1));
}
__device__ __forceinline__ void split_h16(float v, __half& hi, __half& lo) {
    hi = __float2half(v);
    lo = __float2half(v - __half2float(hi));
}

// ---------------- embed: Xf = fp16(64*(concept_emb[cid]+kind_emb[kid])); zero deg ------
__global__ __launch_bounds__(256) void embed_kernel(const int* __restrict__ cid,
                                                    const int* __restrict__ kid,
                                                    const float* __restrict__ cemb,
                                                    const float* __restrict__ kemb) {
    int t = blockIdx.x * 256 + threadIdx.x;        // one float4 per thread
    if (t < NN) g_deg[t] = 0.0f;
    int node = t >> 5;
    int q = t & 31;
    int c = __ldg(cid + node);
    int k = __ldg(kid + node);
    float4 a = __ldg(((const float4*)(cemb + (size_t)c * H)) + q);
    float4 b = __ldg(((const float4*)(kemb + (size_t)k * H)) + q);
    __half h[4];
    h[0] = __float2half(SCALE * (a.x + b.x));
    h[1] = __float2half(SCALE * (a.y + b.y));
    h[2] = __float2half(SCALE * (a.z + b.z));
    h[3] = __float2half(SCALE * (a.w + b.w));
    ((uint2*)g_Xf)[t] = *(const uint2*)h;
}

// ---------------- degree ----------------
__global__ __launch_bounds__(256) void deg_kernel(const int* __restrict__ eidx) {
    int e = blockIdx.x * 256 + threadIdx.x;
    if (e < EDGES) atomicAdd(&g_deg[__ldg(eidx + EDGES + e)], 1.0f);
}

// ---------------- all-weight split conversion (proj + both layers, one launch) --------
// layout: [proj][L0: rel0..7, self][L1: rel0..7, self], each 16384 elems
__global__ __launch_bounds__(256) void convert_w_all_kernel(const float* __restrict__ projW,
                                                            const float* __restrict__ selfW,
                                                            const float* __restrict__ relW) {
    int t = blockIdx.x * 256 + threadIdx.x;
    int f8 = t * 8;
    if (f8 >= NMAT * H * H) return;
    const float* src;
    if (f8 < H * H) {
        src = projW + f8;
    } else {
        int g = f8 - H * H;
        int l = g / ((RREL + 1) * H * H);
        int r = g % ((RREL + 1) * H * H);
        if (r < RREL * H * H) src = relW + (size_t)l * RREL * H * H + r;
        else src = selfW + (size_t)l * H * H + (r - RREL * H * H);
    }
    float4 a = *(const float4*)src;
    float4 b = *(const float4*)(src + 4);
    float v[8] = {a.x, a.y, a.z, a.w, b.x, b.y, b.z, b.w};
    __half hi[8], lo[8];
#pragma unroll
    for (int i = 0; i < 8; i++) split_h16(SCALE * v[i], hi[i], lo[i]);
    ((uint4*)g_Wh)[t] = *(const uint4*)hi;
    ((uint4*)g_Wl)[t] = *(const uint4*)lo;
}

// ---------------- 128x128x128 fp16 2-chain HMMA tile GEMM (pipelined) ----------------
// O[m][g] = sum_k A[m][k]*W[g][k] (scaled ops; /4096 + bias in epilogue).
// A single fp16 (x64); W split hi/lo fp16 (x64). chains: a*wh + a*wl  (residual 2^-11).
// W resident in smem; A streamed in 4 k-chunks of 32 with cp.async double buffer.
// One A chunk = 128 rows x 32 fp16 = 64B/row = 512 uint4 (4 per row).
// OUT_MODE 0: fp32 -> O.  OUT_MODE 1: fp16 x64 -> Oh (in place over A is safe).
template <int OUT_MODE>
__device__ __forceinline__ void tile_gemm(const __half* __restrict__ A_g,
                                          const __half* __restrict__ Wh_g,
                                          const __half* __restrict__ Wl_g,
                                          const float* __restrict__ bias,
                                          float* __restrict__ O,
                                          __half* __restrict__ Oh, int m0) {
    extern __shared__ __half sm[];
    const uint32_t sbase = smem_u32(sm);
    const int tid = threadIdx.x;

    const __half* Ag = A_g + (size_t)m0 * H;

    // ---- prologue: async-load W (hi+lo) and A chunk 0 ----
    {
        const __half* wsrc[2] = {Wh_g, Wl_g};
#pragma unroll
        for (int hl = 0; hl < 2; hl++) {
#pragma unroll
            for (int it = 0; it < 8; it++) {
                int i = tid + it * 256;       // 0..2047 uint4 chunks (16 per row)
                int r = i >> 4;
                int c = i & 15;
                uint32_t dst = sbase + ((hl ? SW_L : SW_H) + r * PITCH_W + c * 8) * 2;
                cp_async16(dst, wsrc[hl] + r * H + c * 8);
            }
        }
#pragma unroll
        for (int it = 0; it < 2; it++) {
            int i = tid + it * 256;           // 0..511
            int r = i >> 2;                   // row 0..127
            int c = i & 3;                    // 16B chunk within 64B row
            uint32_t dst = sbase + (SA_OFF + r * PITCH_A + c * 8) * 2;
            cp_async16(dst, Ag + r * H + c * 8);
        }
        cp_commit();
        cp_wait0();
    }
    __syncthreads();

    const int wid = tid >> 5;
    const int lane = tid & 31;
    const int wm = wid >> 2;       // 0..1 : 64-row block
    const int wn = wid & 3;        // 0..3 : 32-col block

    float acc[4][4][4];
#pragma unroll
    for (int i = 0; i < 4; i++)
#pragma unroll
        for (int j = 0; j < 4; j++)
#pragma unroll
            for (int k = 0; k < 4; k++) acc[i][j][k] = 0.0f;

    const uint32_t lrow = lane & 15;
    const uint32_t lhalf = lane >> 4;          // 0/1 -> +8 fp16
    const uint32_t aWh = sbase + (SW_H + (wn * 32 + lrow) * PITCH_W + lhalf * 8) * 2;
    const uint32_t aWl = sbase + (SW_L + (wn * 32 + lrow) * PITCH_W + lhalf * 8) * 2;
    const uint32_t aA0 = sbase + (SA_OFF + (wm * 64 + lrow) * PITCH_A + lhalf * 8) * 2;

#pragma unroll
    for (int kc = 0; kc < 4; kc++) {
        // issue next A chunk into the other buffer (overlapped with compute)
        if (kc < 3) {
            int b = (kc + 1) & 1;
#pragma unroll
            for (int it = 0; it < 2; it++) {
                int i = tid + it * 256;       // 0..511
                int r = i >> 2;
                int c = i & 3;
                uint32_t dst = sbase + (SA_OFF + b * SA_SZ + r * PITCH_A + c * 8) * 2;
                cp_async16(dst, Ag + r * H + (kc + 1) * 32 + c * 8);
            }
            cp_commit();
        }

        const uint32_t aA = aA0 + (kc & 1) * (SA_SZ * 2);
#pragma unroll
        for (int kstep = 0; kstep < 2; kstep++) {
            const int ks = kc * 2 + kstep;         // global k-step for W
            const uint32_t wkoff = ks * 32;        // 16 fp16 = 32 bytes
            const uint32_t akoff = kstep * 32;
            uint32_t bh[2][4], bl[2][4];
#pragma unroll
            for (int bi = 0; bi < 2; bi++) {
                ldm_x4(bh[bi][0], bh[bi][1], bh[bi][2], bh[bi][3],
                       aWh + bi * (16 * PITCH_W * 2) + wkoff);
                ldm_x4(bl[bi][0], bl[bi][1], bl[bi][2], bl[bi][3],
                       aWl + bi * (16 * PITCH_W * 2) + wkoff);
            }
#pragma unroll
            for (int mi = 0; mi < 4; mi++) {
                uint32_t a[4];
                ldm_x4(a[0], a[1], a[2], a[3], aA + mi * (16 * PITCH_A * 2) + akoff);
#pragma unroll
                for (int bi = 0; bi < 2; bi++) {
                    mma16816(acc[mi][2 * bi + 0], a, bh[bi][0], bh[bi][2]);
                    mma16816(acc[mi][2 * bi + 1], a, bh[bi][1], bh[bi][3]);
                    mma16816(acc[mi][2 * bi + 0], a, bl[bi][0], bl[bi][2]);
                    mma16816(acc[mi][2 * bi + 1], a, bl[bi][1], bl[bi][3]);
                }
            }
        }

        if (kc < 3) {
            cp_wait0();
            __syncthreads();
        }
    }

    // epilogue: unscale (/4096), add bias
    const int gID = lane >> 2;
    const int tig = lane & 3;
#pragma unroll
    for (int mi = 0; mi < 4; mi++) {
#pragma unroll
        for (int nt = 0; nt < 4; nt++) {
            int col = wn * 32 + nt * 8 + tig * 2;
            float b0 = 0.0f, b1 = 0.0f;
            if (bias) { b0 = __ldg(bias + col); b1 = __ldg(bias + col + 1); }
#pragma unroll
            for (int half = 0; half < 2; half++) {
                int row = m0 + wm * 64 + mi * 16 + gID + half * 8;
                float v0 = acc[mi][nt][2 * half + 0] * INV_SCALE2 + b0;
                float v1 = acc[mi][nt][2 * half + 1] * INV_SCALE2 + b1;
                if (OUT_MODE == 0) {
                    float2 fv = make_float2(v0, v1);
                    *(float2*)(O + (size_t)row * H + col) = fv;
                } else {
                    __half2 hv;
                    hv.x = __float2half(SCALE * v0);
                    hv.y = __float2half(SCALE * v1);
                    *(__half2*)(Oh + (size_t)row * H + col) = hv;
                }
            }
        }
    }
}

// proj: Xf = fp16 x64 of (E0 @ projW^T + projb), in-place over Xf
__global__ __launch_bounds__(256, 2) void mma_proj_kernel(const float* __restrict__ projb) {
    tile_gemm<1>(g_Xf, g_Wh, g_Wl, projb, nullptr, g_Xf, blockIdx.x * 128);
}

// grid.y = 9: m<8 -> Y[m] = X @ rel_W[m]^T ; m==8 -> Z = X @ self_W^T + self_b
__global__ __launch_bounds__(256, 2) void mma_layer_kernel(const float* __restrict__ selfb,
                                                           int l) {
    int m = blockIdx.y;
    size_t woff = (size_t)(1 + l * (RREL + 1) + m) * H * H;
    const __half* wh = g_Wh + woff;
    const __half* wl = g_Wl + woff;
    if (m < RREL) {
        tile_gemm<0>(g_Xf, wh, wl, nullptr, g_Y + (size_t)m * NN * H, nullptr,
                     blockIdx.x * 128);
    } else {
        tile_gemm<0>(g_Xf, wh, wl, selfb, g_Z, nullptr, blockIdx.x * 128);
    }
}

// ---------------- edge aggregation: Z[dst] += Y[type][src] / max(deg[dst],1) ----------
__global__ __launch_bounds__(256) void agg_kernel(const int* __restrict__ eidx,
                                                  const int* __restrict__ etype) {
    int e = (blockIdx.x * 256 + threadIdx.x) >> 5;
    int lane = threadIdx.x & 31;
    if (e >= EDGES) return;
    int src = __ldg(eidx + e);
    int dst = __ldg(eidx + EDGES + e);
    int r = __ldg(etype + e);
    float inv = 1.0f / fmaxf(__ldg(&g_deg[dst]), 1.0f);
    const float4* yrow = (const float4*)(g_Y + ((size_t)r * NN + src) * H);
    float4 v = __ldg(yrow + lane);
    v.x *= inv; v.y *= inv; v.z *= inv; v.w *= inv;
    atomicAdd(((float4*)(g_Z + (size_t)dst * H)) + lane, v);
}

// ---------------- relu passes ----------------
// layer 0: Xf = fp16(64 * relu(Z))
__global__ __launch_bounds__(256) void relu_f16_kernel() {
    int t = blockIdx.x * 256 + threadIdx.x;   // float4 index
    float4 z = ((const float4*)g_Z)[t];
    __half h[4];
    h[0] = __float2half(SCALE * fmaxf(z.x, 0.0f));
    h[1] = __float2half(SCALE * fmaxf(z.y, 0.0f));
    h[2] = __float2half(SCALE * fmaxf(z.z, 0.0f));
    h[3] = __float2half(SCALE * fmaxf(z.w, 0.0f));
    ((uint2*)g_Xf)[t] = *(const uint2*)h;
}

// layer 1: out = relu(Z) * mask
__global__ __launch_bounds__(256) void relu_out_kernel(float* __restrict__ out,
                                                       const int* __restrict__ mask) {
    int t = blockIdx.x * 256 + threadIdx.x;
    int node = t >> 5;
    float m = (float)__ldg(mask + node);
    float4 z = ((const float4*)g_Z)[t];
    float4 v;
    v.x = fmaxf(z.x, 0.0f) * m; v.y = fmaxf(z.y, 0.0f) * m;
    v.z = fmaxf(z.z, 0.0f) * m; v.w = fmaxf(z.w, 0.0f) * m;
    ((float4*)out)[t] = v;
}

// ---------------- launch ----------------
extern "C" void kernel_launch(void* const* d_in, const int* in_sizes, int n_in,
                              void* d_out, int out_size) {
    const int* cid     = (const int*)d_in[0];
    const int* kid     = (const int*)d_in[1];
    const int* mask    = (const int*)d_in[2];
    const int* eidx    = (const int*)d_in[3];
    const int* etype   = (const int*)d_in[4];
    const float* cemb  = (const float*)d_in[5];
    const float* kemb  = (const float*)d_in[6];
    const float* projW = (const float*)d_in[7];
    const float* projb = (const float*)d_in[8];
    const float* selfW = (const float*)d_in[9];
    const float* selfb = (const float*)d_in[10];
    const float* relW  = (const float*)d_in[11];
    float* out = (float*)d_out;

    const int smem_bytes = SM_ELEMS * 2;   // 90112
    cudaFuncSetAttribute(mma_proj_kernel, cudaFuncAttributeMaxDynamicSharedMemorySize, smem_bytes);
    cudaFuncSetAttribute(mma_layer_kernel, cudaFuncAttributeMaxDynamicSharedMemorySize, smem_bytes);

    // 1: embed (also zeroes deg)   2: deg   3: all weight conversion   4: proj GEMM
    embed_kernel<<<(NN * 32) / 256, 256>>>(cid, kid, cemb, kemb);
    deg_kernel<<<EDGES / 256, 256>>>(eidx);
    convert_w_all_kernel<<<(NMAT * H * H / 8 + 255) / 256, 256>>>(projW, selfW, relW);
    mma_proj_kernel<<<NN / 128, 256, smem_bytes>>>(projb);

    for (int l = 0; l < NLAYERS; l++) {
        mma_layer_kernel<<<dim3(NN / 128, RREL + 1), 256, smem_bytes>>>(selfb + l * H, l);
        agg_kernel<<<EDGES / 8, 256>>>(eidx, etype);
        if (l == 0)
            relu_f16_kernel<<<(NN * 32) / 256, 256>>>();
        else
            relu_out_kernel<<<(NN * 32) / 256, 256>>>(out, mask);
    }
}

// round 8
// speedup vs baseline: 2.0358x; 1.1131x over previous
#include <cuda_runtime.h>
#include <cuda_fp16.h>
#include <cstdint>
#include <cstddef>

// Problem constants
#define BB 8
#define NSEQ 4096
#define NN 32768            // BB*NSEQ nodes
#define H 128
#define EDGES 524288
#define RREL 8
#define NLAYERS 2

#define PITCH_W 136         // fp16 elems per W smem row (272B)
#define PITCH_A 40          // fp16 elems per A-chunk smem row (80B; 32 data + 8 pad)

// smem map (fp16 element offsets)
#define SW_H   0
#define SW_L   (128 * PITCH_W)                 // 17408
#define SA_OFF (2 * 128 * PITCH_W)             // 34816
#define SA_SZ  (128 * PITCH_A)                 // 5120 per buffer
#define SM_ELEMS (SA_OFF + 2 * SA_SZ)          // 45056 fp16 = 90112 B

#define NMAT (1 + NLAYERS * (RREL + 1))        // 19 weight matrices
#define SCALE 64.0f
#define INV_SCALE2 (1.0f / 4096.0f)

// ---------------- scratch (static device globals; no allocation) ----------------
__device__ float g_Z[(size_t)NN * H];            // self-GEMM out / agg accumulator (16 MB)
__device__ float g_Y[(size_t)RREL * NN * H];     // per-relation transformed states (128 MB)
__device__ __half g_Xf[(size_t)NN * H];          // node states, fp16 scaled x64 (8 MB)
__device__ __half g_Wh[(size_t)NMAT * H * H];    // weight hi splits (x64)
__device__ __half g_Wl[(size_t)NMAT * H * H];    // weight lo splits
__device__ float g_deg[NN];

// ---------------- helpers ----------------
__device__ __forceinline__ uint32_t smem_u32(const void* p) {
    uint32_t a;
    asm("{ .reg .u64 t; cvta.to.shared.u64 t, %1; cvt.u32.u64 %0, t; }" : "=r"(a) : "l"(p));
    return a;
}
__device__ __forceinline__ void cp_async16(uint32_t dst, const void* src) {
    asm volatile("cp.async.cg.shared.global [%0], [%1], 16;" :: "r"(dst), "l"(src));
}
__device__ __forceinline__ void cp_commit() {
    asm volatile("cp.async.commit_group;");
}
__device__ __forceinline__ void cp_wait0() {
    asm volatile("cp.async.wait_group 0;");
}
__device__ __forceinline__ void ldm_x4(uint32_t& r0, uint32_t& r1, uint32_t& r2, uint32_t& r3,
                                       uint32_t addr) {
    asm volatile("ldmatrix.sync.aligned.m8n8.x4.shared.b16 {%0,%1,%2,%3}, [%4];"
                 : "=r"(r0), "=r"(r1), "=r"(r2), "=r"(r3) : "r"(addr));
}
__device__ __forceinline__ void mma16816(float* d, const uint32_t* a, uint32_t b0, uint32_t b1) {
    asm volatile(
        "mma.sync.aligned.m16n8k16.row.col.f32.f16.f16.f32 "
        "{%0,%1,%2,%3}, {%4,%5,%6,%7}, {%8,%9}, {%0,%1,%2,%3};"
        : "+f"(d[0]), "+f"(d[1]), "+f"(d[2]), "+f"(d[3])
        : "r"(a[0]), "r"(a[1]), "r"(a[2]), "r"(a[3]), "r"(b0), "r"(b1));
}
__device__ __forceinline__ void split_h16(float v, __half& hi, __half& lo) {
    hi = __float2half(v);
    lo = __float2half(v - __half2float(hi));
}

// ---------------- embed: Xf = fp16(64*(concept_emb[cid]+kind_emb[kid])); zero deg ------
__global__ __launch_bounds__(256) void embed_kernel(const int* __restrict__ cid,
                                                    const int* __restrict__ kid,
                                                    const float* __restrict__ cemb,
                                                    const float* __restrict__ kemb) {
    int t = blockIdx.x * 256 + threadIdx.x;        // one float4 per thread
    if (t < NN) g_deg[t] = 0.0f;
    int node = t >> 5;
    int q = t & 31;
    int c = __ldg(cid + node);
    int k = __ldg(kid + node);
    float4 a = __ldg(((const float4*)(cemb + (size_t)c * H)) + q);
    float4 b = __ldg(((const float4*)(kemb + (size_t)k * H)) + q);
    __half h[4];
    h[0] = __float2half(SCALE * (a.x + b.x));
    h[1] = __float2half(SCALE * (a.y + b.y));
    h[2] = __float2half(SCALE * (a.z + b.z));
    h[3] = __float2half(SCALE * (a.w + b.w));
    ((uint2*)g_Xf)[t] = *(const uint2*)h;
}

// ---------------- degree ----------------
__global__ __launch_bounds__(256) void deg_kernel(const int* __restrict__ eidx) {
    int e = blockIdx.x * 256 + threadIdx.x;
    if (e < EDGES) atomicAdd(&g_deg[__ldg(eidx + EDGES + e)], 1.0f);
}

// ---------------- all-weight split conversion (proj + both layers, one launch) --------
// layout: [proj][L0: rel0..7, self][L1: rel0..7, self], each 16384 elems
__global__ __launch_bounds__(256) void convert_w_all_kernel(const float* __restrict__ projW,
                                                            const float* __restrict__ selfW,
                                                            const float* __restrict__ relW) {
    int t = blockIdx.x * 256 + threadIdx.x;
    int f8 = t * 8;
    if (f8 >= NMAT * H * H) return;
    const float* src;
    if (f8 < H * H) {
        src = projW + f8;
    } else {
        int g = f8 - H * H;
        int l = g / ((RREL + 1) * H * H);
        int r = g % ((RREL + 1) * H * H);
        if (r < RREL * H * H) src = relW + (size_t)l * RREL * H * H + r;
        else src = selfW + (size_t)l * H * H + (r - RREL * H * H);
    }
    float4 a = *(const float4*)src;
    float4 b = *(const float4*)(src + 4);
    float v[8] = {a.x, a.y, a.z, a.w, b.x, b.y, b.z, b.w};
    __half hi[8], lo[8];
#pragma unroll
    for (int i = 0; i < 8; i++) split_h16(SCALE * v[i], hi[i], lo[i]);
    ((uint4*)g_Wh)[t] = *(const uint4*)hi;
    ((uint4*)g_Wl)[t] = *(const uint4*)lo;
}

// ---------------- 128x128x128 fp16 HMMA tile GEMM (pipelined) ----------------
// O[m][g] = sum_k A[m][k]*W[g][k] (scaled ops; /4096 + bias in epilogue).
// A single fp16 (x64); W hi (+ optional lo) fp16 (x64).
// CHAINS=2: a*wh + a*wl (residual 2^-22-ish). CHAINS=1: a*wh only (residual 2^-11).
// W resident in smem; A streamed in 4 k-chunks of 32 with cp.async double buffer.
// OUT_MODE 0: fp32 -> O.  OUT_MODE 1: fp16 x64 -> Oh (in place over A is safe).
template <int OUT_MODE, int CHAINS>
__device__ __forceinline__ void tile_gemm(const __half* __restrict__ A_g,
                                          const __half* __restrict__ Wh_g,
                                          const __half* __restrict__ Wl_g,
                                          const float* __restrict__ bias,
                                          float* __restrict__ O,
                                          __half* __restrict__ Oh, int m0) {
    extern __shared__ __half sm[];
    const uint32_t sbase = smem_u32(sm);
    const int tid = threadIdx.x;

    const __half* Ag = A_g + (size_t)m0 * H;

    // ---- prologue: async-load W (hi, and lo if CHAINS==2) and A chunk 0 ----
    {
        const __half* wsrc[2] = {Wh_g, Wl_g};
#pragma unroll
        for (int hl = 0; hl < CHAINS; hl++) {
#pragma unroll
            for (int it = 0; it < 8; it++) {
                int i = tid + it * 256;       // 0..2047 uint4 chunks (16 per row)
                int r = i >> 4;
                int c = i & 15;
                uint32_t dst = sbase + ((hl ? SW_L : SW_H) + r * PITCH_W + c * 8) * 2;
                cp_async16(dst, wsrc[hl] + r * H + c * 8);
            }
        }
#pragma unroll
        for (int it = 0; it < 2; it++) {
            int i = tid + it * 256;           // 0..511
            int r = i >> 2;                   // row 0..127
            int c = i & 3;                    // 16B chunk within 64B row
            uint32_t dst = sbase + (SA_OFF + r * PITCH_A + c * 8) * 2;
            cp_async16(dst, Ag + r * H + c * 8);
        }
        cp_commit();
        cp_wait0();
    }
    __syncthreads();

    const int wid = tid >> 5;
    const int lane = tid & 31;
    const int wm = wid >> 2;       // 0..1 : 64-row block
    const int wn = wid & 3;        // 0..3 : 32-col block

    float acc[4][4][4];
#pragma unroll
    for (int i = 0; i < 4; i++)
#pragma unroll
        for (int j = 0; j < 4; j++)
#pragma unroll
            for (int k = 0; k < 4; k++) acc[i][j][k] = 0.0f;

    const uint32_t lrow = lane & 15;
    const uint32_t lhalf = lane >> 4;          // 0/1 -> +8 fp16
    const uint32_t aWh = sbase + (SW_H + (wn * 32 + lrow) * PITCH_W + lhalf * 8) * 2;
    const uint32_t aWl = sbase + (SW_L + (wn * 32 + lrow) * PITCH_W + lhalf * 8) * 2;
    const uint32_t aA0 = sbase + (SA_OFF + (wm * 64 + lrow) * PITCH_A + lhalf * 8) * 2;

#pragma unroll
    for (int kc = 0; kc < 4; kc++) {
        // issue next A chunk into the other buffer (overlapped with compute)
        if (kc < 3) {
            int b = (kc + 1) & 1;
#pragma unroll
            for (int it = 0; it < 2; it++) {
                int i = tid + it * 256;       // 0..511
                int r = i >> 2;
                int c = i & 3;
                uint32_t dst = sbase + (SA_OFF + b * SA_SZ + r * PITCH_A + c * 8) * 2;
                cp_async16(dst, Ag + r * H + (kc + 1) * 32 + c * 8);
            }
            cp_commit();
        }

        const uint32_t aA = aA0 + (kc & 1) * (SA_SZ * 2);
#pragma unroll
        for (int kstep = 0; kstep < 2; kstep++) {
            const int ks = kc * 2 + kstep;         // global k-step for W
            const uint32_t wkoff = ks * 32;        // 16 fp16 = 32 bytes
            const uint32_t akoff = kstep * 32;
            uint32_t bh[2][4], bl[2][4];
#pragma unroll
            for (int bi = 0; bi < 2; bi++) {
                ldm_x4(bh[bi][0], bh[bi][1], bh[bi][2], bh[bi][3],
                       aWh + bi * (16 * PITCH_W * 2) + wkoff);
                if (CHAINS == 2) {
                    ldm_x4(bl[bi][0], bl[bi][1], bl[bi][2], bl[bi][3],
                           aWl + bi * (16 * PITCH_W * 2) + wkoff);
                }
            }
#pragma unroll
            for (int mi = 0; mi < 4; mi++) {
                uint32_t a[4];
                ldm_x4(a[0], a[1], a[2], a[3], aA + mi * (16 * PITCH_A * 2) + akoff);
#pragma unroll
                for (int bi = 0; bi < 2; bi++) {
                    mma16816(acc[mi][2 * bi + 0], a, bh[bi][0], bh[bi][2]);
                    mma16816(acc[mi][2 * bi + 1], a, bh[bi][1], bh[bi][3]);
                    if (CHAINS == 2) {
                        mma16816(acc[mi][2 * bi + 0], a, bl[bi][0], bl[bi][2]);
                        mma16816(acc[mi][2 * bi + 1], a, bl[bi][1], bl[bi][3]);
                    }
                }
            }
        }

        if (kc < 3) {
            cp_wait0();
            __syncthreads();
        }
    }

    // epilogue: unscale (/4096), add bias
    const int gID = lane >> 2;
    const int tig = lane & 3;
#pragma unroll
    for (int mi = 0; mi < 4; mi++) {
#pragma unroll
        for (int nt = 0; nt < 4; nt++) {
            int col = wn * 32 + nt * 8 + tig * 2;
            float b0 = 0.0f, b1 = 0.0f;
            if (bias) { b0 = __ldg(bias + col); b1 = __ldg(bias + col + 1); }
#pragma unroll
            for (int half = 0; half < 2; half++) {
                int row = m0 + wm * 64 + mi * 16 + gID + half * 8;
                float v0 = acc[mi][nt][2 * half + 0] * INV_SCALE2 + b0;
                float v1 = acc[mi][nt][2 * half + 1] * INV_SCALE2 + b1;
                if (OUT_MODE == 0) {
                    float2 fv = make_float2(v0, v1);
                    *(float2*)(O + (size_t)row * H + col) = fv;
                } else {
                    __half2 hv;
                    hv.x = __float2half(SCALE * v0);
                    hv.y = __float2half(SCALE * v1);
                    *(__half2*)(Oh + (size_t)row * H + col) = hv;
                }
            }
        }
    }
}

// proj: Xf = fp16 x64 of (E0 @ projW^T + projb), in-place over Xf (2-chain)
__global__ __launch_bounds__(256, 2) void mma_proj_kernel(const float* __restrict__ projb) {
    tile_gemm<1, 2>(g_Xf, g_Wh, g_Wl, projb, nullptr, g_Xf, blockIdx.x * 128);
}

// grid.y = 9: m<8 -> Y[m] = X @ rel_W[m]^T (1-chain) ; m==8 -> Z = X @ self_W^T + b (2-chain)
__global__ __launch_bounds__(256, 2) void mma_layer_kernel(const float* __restrict__ selfb,
                                                           int l) {
    int m = blockIdx.y;
    size_t woff = (size_t)(1 + l * (RREL + 1) + m) * H * H;
    const __half* wh = g_Wh + woff;
    const __half* wl = g_Wl + woff;
    if (m < RREL) {
        tile_gemm<0, 1>(g_Xf, wh, wl, nullptr, g_Y + (size_t)m * NN * H, nullptr,
                        blockIdx.x * 128);
    } else {
        tile_gemm<0, 2>(g_Xf, wh, wl, selfb, g_Z, nullptr, blockIdx.x * 128);
    }
}

// ---------------- edge aggregation: Z[dst] += Y[type][src] / max(deg[dst],1) ----------
__global__ __launch_bounds__(256) void agg_kernel(const int* __restrict__ eidx,
                                                  const int* __restrict__ etype) {
    int e = (blockIdx.x * 256 + threadIdx.x) >> 5;
    int lane = threadIdx.x & 31;
    if (e >= EDGES) return;
    int src = __ldg(eidx + e);
    int dst = __ldg(eidx + EDGES + e);
    int r = __ldg(etype + e);
    float inv = 1.0f / fmaxf(__ldg(&g_deg[dst]), 1.0f);
    const float4* yrow = (const float4*)(g_Y + ((size_t)r * NN + src) * H);
    float4 v = __ldg(yrow + lane);
    v.x *= inv; v.y *= inv; v.z *= inv; v.w *= inv;
    atomicAdd(((float4*)(g_Z + (size_t)dst * H)) + lane, v);
}

// ---------------- relu passes ----------------
// layer 0: Xf = fp16(64 * relu(Z))
__global__ __launch_bounds__(256) void relu_f16_kernel() {
    int t = blockIdx.x * 256 + threadIdx.x;   // float4 index
    float4 z = ((const float4*)g_Z)[t];
    __half h[4];
    h[0] = __float2half(SCALE * fmaxf(z.x, 0.0f));
    h[1] = __float2half(SCALE * fmaxf(z.y, 0.0f));
    h[2] = __float2half(SCALE * fmaxf(z.z, 0.0f));
    h[3] = __float2half(SCALE * fmaxf(z.w, 0.0f));
    ((uint2*)g_Xf)[t] = *(const uint2*)h;
}

// layer 1: out = relu(Z) * mask
__global__ __launch_bounds__(256) void relu_out_kernel(float* __restrict__ out,
                                                       const int* __restrict__ mask) {
    int t = blockIdx.x * 256 + threadIdx.x;
    int node = t >> 5;
    float m = (float)__ldg(mask + node);
    float4 z = ((const float4*)g_Z)[t];
    float4 v;
    v.x = fmaxf(z.x, 0.0f) * m; v.y = fmaxf(z.y, 0.0f) * m;
    v.z = fmaxf(z.z, 0.0f) * m; v.w = fmaxf(z.w, 0.0f) * m;
    ((float4*)out)[t] = v;
}

// ---------------- launch ----------------
extern "C" void kernel_launch(void* const* d_in, const int* in_sizes, int n_in,
                              void* d_out, int out_size) {
    const int* cid     = (const int*)d_in[0];
    const int* kid     = (const int*)d_in[1];
    const int* mask    = (const int*)d_in[2];
    const int* eidx    = (const int*)d_in[3];
    const int* etype   = (const int*)d_in[4];
    const float* cemb  = (const float*)d_in[5];
    const float* kemb  = (const float*)d_in[6];
    const float* projW = (const float*)d_in[7];
    const float* projb = (const float*)d_in[8];
    const float* selfW = (const float*)d_in[9];
    const float* selfb = (const float*)d_in[10];
    const float* relW  = (const float*)d_in[11];
    float* out = (float*)d_out;

    const int smem_bytes = SM_ELEMS * 2;   // 90112
    cudaFuncSetAttribute(mma_proj_kernel, cudaFuncAttributeMaxDynamicSharedMemorySize, smem_bytes);
    cudaFuncSetAttribute(mma_layer_kernel, cudaFuncAttributeMaxDynamicSharedMemorySize, smem_bytes);

    // 1: embed (also zeroes deg)   2: deg   3: all weight conversion   4: proj GEMM
    embed_kernel<<<(NN * 32) / 256, 256>>>(cid, kid, cemb, kemb);
    deg_kernel<<<EDGES / 256, 256>>>(eidx);
    convert_w_all_kernel<<<(NMAT * H * H / 8 + 255) / 256, 256>>>(projW, selfW, relW);
    mma_proj_kernel<<<NN / 128, 256, smem_bytes>>>(projb);

    for (int l = 0; l < NLAYERS; l++) {
        mma_layer_kernel<<<dim3(NN / 128, RREL + 1), 256, smem_bytes>>>(selfb + l * H, l);
        agg_kernel<<<EDGES / 8, 256>>>(eidx, etype);
        if (l == 0)
            relu_f16_kernel<<<(NN * 32) / 256, 256>>>();
        else
            relu_out_kernel<<<(NN * 32) / 256, 256>>>(out, mask);
    }
}

// round 9
// speedup vs baseline: 2.1923x; 1.0769x over previous
#include <cuda_runtime.h>
#include <cuda_fp16.h>
#include <cstdint>
#include <cstddef>

// Problem constants
#define BB 8
#define NSEQ 4096
#define NN 32768            // BB*NSEQ nodes
#define H 128
#define EDGES 524288
#define RREL 8
#define NLAYERS 2

#define PITCH_W 136         // fp16 elems per W smem row (272B)
#define PITCH_A 40          // fp16 elems per A-chunk smem row (80B; 32 data + 8 pad)

// smem map (fp16 element offsets)
#define SW_H   0
#define SW_L   (128 * PITCH_W)                 // 17408
#define SA_OFF (2 * 128 * PITCH_W)             // 34816
#define SA_SZ  (128 * PITCH_A)                 // 5120 per buffer
#define SM_ELEMS (SA_OFF + 2 * SA_SZ)          // 45056 fp16 = 90112 B

#define NMAT (1 + NLAYERS * (RREL + 1))        // 19 weight matrices
#define SCALE 64.0f
#define INV_SCALE2 (1.0f / 4096.0f)

// ---------------- scratch (static device globals; no allocation) ----------------
__device__ float g_Z[(size_t)NN * H];            // self-GEMM out / agg accumulator (16 MB)
__device__ __half g_Y[(size_t)RREL * NN * H];    // per-relation messages, fp16 (64 MB)
__device__ __half g_Xf[(size_t)NN * H];          // node states, fp16 scaled x64 (8 MB)
__device__ __half g_Wh[(size_t)NMAT * H * H];    // weight hi splits (x64)
__device__ __half g_Wl[(size_t)NMAT * H * H];    // weight lo splits
__device__ float g_deg[NN];

// ---------------- helpers ----------------
__device__ __forceinline__ uint32_t smem_u32(const void* p) {
    uint32_t a;
    asm("{ .reg .u64 t; cvta.to.shared.u64 t, %1; cvt.u32.u64 %0, t; }" : "=r"(a) : "l"(p));
    return a;
}
__device__ __forceinline__ void cp_async16(uint32_t dst, const void* src) {
    asm volatile("cp.async.cg.shared.global [%0], [%1], 16;" :: "r"(dst), "l"(src));
}
__device__ __forceinline__ void cp_commit() {
    asm volatile("cp.async.commit_group;");
}
__device__ __forceinline__ void cp_wait0() {
    asm volatile("cp.async.wait_group 0;");
}
__device__ __forceinline__ void ldm_x4(uint32_t& r0, uint32_t& r1, uint32_t& r2, uint32_t& r3,
                                       uint32_t addr) {
    asm volatile("ldmatrix.sync.aligned.m8n8.x4.shared.b16 {%0,%1,%2,%3}, [%4];"
                 : "=r"(r0), "=r"(r1), "=r"(r2), "=r"(r3) : "r"(addr));
}
__device__ __forceinline__ void mma16816(float* d, const uint32_t* a, uint32_t b0, uint32_t b1) {
    asm volatile(
        "mma.sync.aligned.m16n8k16.row.col.f32.f16.f16.f32 "
        "{%0,%1,%2,%3}, {%4,%5,%6,%7}, {%8,%9}, {%0,%1,%2,%3};"
        : "+f"(d[0]), "+f"(d[1]), "+f"(d[2]), "+f"(d[3])
        : "r"(a[0]), "r"(a[1]), "r"(a[2]), "r"(a[3]), "r"(b0), "r"(b1));
}
__device__ __forceinline__ void split_h16(float v, __half& hi, __half& lo) {
    hi = __float2half(v);
    lo = __float2half(v - __half2float(hi));
}

// ---------------- embed: Xf = fp16(64*(concept_emb[cid]+kind_emb[kid])); zero deg ------
__global__ __launch_bounds__(256) void embed_kernel(const int* __restrict__ cid,
                                                    const int* __restrict__ kid,
                                                    const float* __restrict__ cemb,
                                                    const float* __restrict__ kemb) {
    int t = blockIdx.x * 256 + threadIdx.x;        // one float4 per thread
    if (t < NN) g_deg[t] = 0.0f;
    int node = t >> 5;
    int q = t & 31;
    int c = __ldg(cid + node);
    int k = __ldg(kid + node);
    float4 a = __ldg(((const float4*)(cemb + (size_t)c * H)) + q);
    float4 b = __ldg(((const float4*)(kemb + (size_t)k * H)) + q);
    __half h[4];
    h[0] = __float2half(SCALE * (a.x + b.x));
    h[1] = __float2half(SCALE * (a.y + b.y));
    h[2] = __float2half(SCALE * (a.z + b.z));
    h[3] = __float2half(SCALE * (a.w + b.w));
    ((uint2*)g_Xf)[t] = *(const uint2*)h;
}

// ---------------- degree ----------------
__global__ __launch_bounds__(256) void deg_kernel(const int* __restrict__ eidx) {
    int e = blockIdx.x * 256 + threadIdx.x;
    if (e < EDGES) atomicAdd(&g_deg[__ldg(eidx + EDGES + e)], 1.0f);
}

// ---------------- all-weight split conversion (proj + both layers, one launch) --------
// layout: [proj][L0: rel0..7, self][L1: rel0..7, self], each 16384 elems
__global__ __launch_bounds__(256) void convert_w_all_kernel(const float* __restrict__ projW,
                                                            const float* __restrict__ selfW,
                                                            const float* __restrict__ relW) {
    int t = blockIdx.x * 256 + threadIdx.x;
    int f8 = t * 8;
    if (f8 >= NMAT * H * H) return;
    const float* src;
    if (f8 < H * H) {
        src = projW + f8;
    } else {
        int g = f8 - H * H;
        int l = g / ((RREL + 1) * H * H);
        int r = g % ((RREL + 1) * H * H);
        if (r < RREL * H * H) src = relW + (size_t)l * RREL * H * H + r;
        else src = selfW + (size_t)l * H * H + (r - RREL * H * H);
    }
    float4 a = *(const float4*)src;
    float4 b = *(const float4*)(src + 4);
    float v[8] = {a.x, a.y, a.z, a.w, b.x, b.y, b.z, b.w};
    __half hi[8], lo[8];
#pragma unroll
    for (int i = 0; i < 8; i++) split_h16(SCALE * v[i], hi[i], lo[i]);
    ((uint4*)g_Wh)[t] = *(const uint4*)hi;
    ((uint4*)g_Wl)[t] = *(const uint4*)lo;
}

// ---------------- 128x128x128 fp16 HMMA tile GEMM (pipelined) ----------------
// O[m][g] = sum_k A[m][k]*W[g][k] (scaled ops; /4096 + bias in epilogue).
// A single fp16 (x64); W hi (+ optional lo) fp16 (x64).
// CHAINS=2: a*wh + a*wl. CHAINS=1: a*wh only (residual 2^-11).
// W resident in smem; A streamed in 4 k-chunks of 32 with cp.async double buffer.
// OUT_MODE 0: fp32 -> O (+bias).  OUT_MODE 1: fp16 x64 -> Oh (+bias; in place over A ok).
// OUT_MODE 2: fp16 unscaled -> Oh (no bias).
template <int OUT_MODE, int CHAINS>
__device__ __forceinline__ void tile_gemm(const __half* __restrict__ A_g,
                                          const __half* __restrict__ Wh_g,
                                          const __half* __restrict__ Wl_g,
                                          const float* __restrict__ bias,
                                          float* __restrict__ O,
                                          __half* __restrict__ Oh, int m0) {
    extern __shared__ __half sm[];
    const uint32_t sbase = smem_u32(sm);
    const int tid = threadIdx.x;

    const __half* Ag = A_g + (size_t)m0 * H;

    // ---- prologue: async-load W (hi, and lo if CHAINS==2) and A chunk 0 ----
    {
        const __half* wsrc[2] = {Wh_g, Wl_g};
#pragma unroll
        for (int hl = 0; hl < CHAINS; hl++) {
#pragma unroll
            for (int it = 0; it < 8; it++) {
                int i = tid + it * 256;       // 0..2047 uint4 chunks (16 per row)
                int r = i >> 4;
                int c = i & 15;
                uint32_t dst = sbase + ((hl ? SW_L : SW_H) + r * PITCH_W + c * 8) * 2;
                cp_async16(dst, wsrc[hl] + r * H + c * 8);
            }
        }
#pragma unroll
        for (int it = 0; it < 2; it++) {
            int i = tid + it * 256;           // 0..511
            int r = i >> 2;                   // row 0..127
            int c = i & 3;                    // 16B chunk within 64B row
            uint32_t dst = sbase + (SA_OFF + r * PITCH_A + c * 8) * 2;
            cp_async16(dst, Ag + r * H + c * 8);
        }
        cp_commit();
        cp_wait0();
    }
    __syncthreads();

    const int wid = tid >> 5;
    const int lane = tid & 31;
    const int wm = wid >> 2;       // 0..1 : 64-row block
    const int wn = wid & 3;        // 0..3 : 32-col block

    float acc[4][4][4];
#pragma unroll
    for (int i = 0; i < 4; i++)
#pragma unroll
        for (int j = 0; j < 4; j++)
#pragma unroll
            for (int k = 0; k < 4; k++) acc[i][j][k] = 0.0f;

    const uint32_t lrow = lane & 15;
    const uint32_t lhalf = lane >> 4;          // 0/1 -> +8 fp16
    const uint32_t aWh = sbase + (SW_H + (wn * 32 + lrow) * PITCH_W + lhalf * 8) * 2;
    const uint32_t aWl = sbase + (SW_L + (wn * 32 + lrow) * PITCH_W + lhalf * 8) * 2;
    const uint32_t aA0 = sbase + (SA_OFF + (wm * 64 + lrow) * PITCH_A + lhalf * 8) * 2;

#pragma unroll
    for (int kc = 0; kc < 4; kc++) {
        // issue next A chunk into the other buffer (overlapped with compute)
        if (kc < 3) {
            int b = (kc + 1) & 1;
#pragma unroll
            for (int it = 0; it < 2; it++) {
                int i = tid + it * 256;       // 0..511
                int r = i >> 2;
                int c = i & 3;
                uint32_t dst = sbase + (SA_OFF + b * SA_SZ + r * PITCH_A + c * 8) * 2;
                cp_async16(dst, Ag + r * H + (kc + 1) * 32 + c * 8);
            }
            cp_commit();
        }

        const uint32_t aA = aA0 + (kc & 1) * (SA_SZ * 2);
#pragma unroll
        for (int kstep = 0; kstep < 2; kstep++) {
            const int ks = kc * 2 + kstep;         // global k-step for W
            const uint32_t wkoff = ks * 32;        // 16 fp16 = 32 bytes
            const uint32_t akoff = kstep * 32;
            uint32_t bh[2][4], bl[2][4];
#pragma unroll
            for (int bi = 0; bi < 2; bi++) {
                ldm_x4(bh[bi][0], bh[bi][1], bh[bi][2], bh[bi][3],
                       aWh + bi * (16 * PITCH_W * 2) + wkoff);
                if (CHAINS == 2) {
                    ldm_x4(bl[bi][0], bl[bi][1], bl[bi][2], bl[bi][3],
                           aWl + bi * (16 * PITCH_W * 2) + wkoff);
                }
            }
#pragma unroll
            for (int mi = 0; mi < 4; mi++) {
                uint32_t a[4];
                ldm_x4(a[0], a[1], a[2], a[3], aA + mi * (16 * PITCH_A * 2) + akoff);
#pragma unroll
                for (int bi = 0; bi < 2; bi++) {
                    mma16816(acc[mi][2 * bi + 0], a, bh[bi][0], bh[bi][2]);
                    mma16816(acc[mi][2 * bi + 1], a, bh[bi][1], bh[bi][3]);
                    if (CHAINS == 2) {
                        mma16816(acc[mi][2 * bi + 0], a, bl[bi][0], bl[bi][2]);
                        mma16816(acc[mi][2 * bi + 1], a, bl[bi][1], bl[bi][3]);
                    }
                }
            }
        }

        if (kc < 3) {
            cp_wait0();
            __syncthreads();
        }
    }

    // epilogue: unscale (/4096), add bias (modes 0/1)
    const int gID = lane >> 2;
    const int tig = lane & 3;
#pragma unroll
    for (int mi = 0; mi < 4; mi++) {
#pragma unroll
        for (int nt = 0; nt < 4; nt++) {
            int col = wn * 32 + nt * 8 + tig * 2;
            float b0 = 0.0f, b1 = 0.0f;
            if (OUT_MODE != 2 && bias) { b0 = __ldg(bias + col); b1 = __ldg(bias + col + 1); }
#pragma unroll
            for (int half = 0; half < 2; half++) {
                int row = m0 + wm * 64 + mi * 16 + gID + half * 8;
                float v0 = acc[mi][nt][2 * half + 0] * INV_SCALE2 + b0;
                float v1 = acc[mi][nt][2 * half + 1] * INV_SCALE2 + b1;
                if (OUT_MODE == 0) {
                    float2 fv = make_float2(v0, v1);
                    *(float2*)(O + (size_t)row * H + col) = fv;
                } else if (OUT_MODE == 1) {
                    __half2 hv;
                    hv.x = __float2half(SCALE * v0);
                    hv.y = __float2half(SCALE * v1);
                    *(__half2*)(Oh + (size_t)row * H + col) = hv;
                } else {
                    __half2 hv;
                    hv.x = __float2half(v0);
                    hv.y = __float2half(v1);
                    *(__half2*)(Oh + (size_t)row * H + col) = hv;
                }
            }
        }
    }
}

// proj: Xf = fp16 x64 of (E0 @ projW^T + projb), in-place over Xf (2-chain)
__global__ __launch_bounds__(256, 2) void mma_proj_kernel(const float* __restrict__ projb) {
    tile_gemm<1, 2>(g_Xf, g_Wh, g_Wl, projb, nullptr, g_Xf, blockIdx.x * 128);
}

// grid.y = 9: m<8 -> Y[m] = X @ rel_W[m]^T (1-chain, fp16 out) ; m==8 -> Z (2-chain, fp32)
__global__ __launch_bounds__(256, 2) void mma_layer_kernel(const float* __restrict__ selfb,
                                                           int l) {
    int m = blockIdx.y;
    size_t woff = (size_t)(1 + l * (RREL + 1) + m) * H * H;
    const __half* wh = g_Wh + woff;
    const __half* wl = g_Wl + woff;
    if (m < RREL) {
        tile_gemm<2, 1>(g_Xf, wh, wl, nullptr, nullptr, g_Y + (size_t)m * NN * H,
                        blockIdx.x * 128);
    } else {
        tile_gemm<0, 2>(g_Xf, wh, wl, selfb, g_Z, nullptr, blockIdx.x * 128);
    }
}

// ---------------- edge aggregation: Z[dst] += Y[type][src] / max(deg[dst],1) ----------
// Y fp16: warp per edge, lane loads uint2 (4 halves = 8B), REDs fp32 float4 into Z.
__global__ __launch_bounds__(256) void agg_kernel(const int* __restrict__ eidx,
                                                  const int* __restrict__ etype) {
    int e = (blockIdx.x * 256 + threadIdx.x) >> 5;
    int lane = threadIdx.x & 31;
    if (e >= EDGES) return;
    int src = __ldg(eidx + e);
    int dst = __ldg(eidx + EDGES + e);
    int r = __ldg(etype + e);
    float inv = 1.0f / fmaxf(__ldg(&g_deg[dst]), 1.0f);
    const uint2* yrow = (const uint2*)(g_Y + ((size_t)r * NN + src) * H);
    uint2 u = __ldg(yrow + lane);
    __half2 h0 = *(__half2*)&u.x;
    __half2 h1 = *(__half2*)&u.y;
    float2 f0 = __half22float2(h0);
    float2 f1 = __half22float2(h1);
    float4 v;
    v.x = f0.x * inv; v.y = f0.y * inv; v.z = f1.x * inv; v.w = f1.y * inv;
    atomicAdd(((float4*)(g_Z + (size_t)dst * H)) + lane, v);
}

// ---------------- relu passes ----------------
// layer 0: Xf = fp16(64 * relu(Z))
__global__ __launch_bounds__(256) void relu_f16_kernel() {
    int t = blockIdx.x * 256 + threadIdx.x;   // float4 index
    float4 z = ((const float4*)g_Z)[t];
    __half h[4];
    h[0] = __float2half(SCALE * fmaxf(z.x, 0.0f));
    h[1] = __float2half(SCALE * fmaxf(z.y, 0.0f));
    h[2] = __float2half(SCALE * fmaxf(z.z, 0.0f));
    h[3] = __float2half(SCALE * fmaxf(z.w, 0.0f));
    ((uint2*)g_Xf)[t] = *(const uint2*)h;
}

// layer 1: out = relu(Z) * mask
__global__ __launch_bounds__(256) void relu_out_kernel(float* __restrict__ out,
                                                       const int* __restrict__ mask) {
    int t = blockIdx.x * 256 + threadIdx.x;
    int node = t >> 5;
    float m = (float)__ldg(mask + node);
    float4 z = ((const float4*)g_Z)[t];
    float4 v;
    v.x = fmaxf(z.x, 0.0f) * m; v.y = fmaxf(z.y, 0.0f) * m;
    v.z = fmaxf(z.z, 0.0f) * m; v.w = fmaxf(z.w, 0.0f) * m;
    ((float4*)out)[t] = v;
}

// ---------------- launch ----------------
extern "C" void kernel_launch(void* const* d_in, const int* in_sizes, int n_in,
                              void* d_out, int out_size) {
    const int* cid     = (const int*)d_in[0];
    const int* kid     = (const int*)d_in[1];
    const int* mask    = (const int*)d_in[2];
    const int* eidx    = (const int*)d_in[3];
    const int* etype   = (const int*)d_in[4];
    const float* cemb  = (const float*)d_in[5];
    const float* kemb  = (const float*)d_in[6];
    const float* projW = (const float*)d_in[7];
    const float* projb = (const float*)d_in[8];
    const float* selfW = (const float*)d_in[9];
    const float* selfb = (const float*)d_in[10];
    const float* relW  = (const float*)d_in[11];
    float* out = (float*)d_out;

    const int smem_bytes = SM_ELEMS * 2;   // 90112
    cudaFuncSetAttribute(mma_proj_kernel, cudaFuncAttributeMaxDynamicSharedMemorySize, smem_bytes);
    cudaFuncSetAttribute(mma_layer_kernel, cudaFuncAttributeMaxDynamicSharedMemorySize, smem_bytes);

    // 1: embed (also zeroes deg)   2: deg   3: all weight conversion   4: proj GEMM
    embed_kernel<<<(NN * 32) / 256, 256>>>(cid, kid, cemb, kemb);
    deg_kernel<<<EDGES / 256, 256>>>(eidx);
    convert_w_all_kernel<<<(NMAT * H * H / 8 + 255) / 256, 256>>>(projW, selfW, relW);
    mma_proj_kernel<<<NN / 128, 256, smem_bytes>>>(projb);

    for (int l = 0; l < NLAYERS; l++) {
        mma_layer_kernel<<<dim3(NN / 128, RREL + 1), 256, smem_bytes>>>(selfb + l * H, l);
        agg_kernel<<<EDGES / 8, 256>>>(eidx, etype);
        if (l == 0)
            relu_f16_kernel<<<(NN * 32) / 256, 256>>>();
        else
            relu_out_kernel<<<(NN * 32) / 256, 256>>>(out, mask);
    }
}